// round 3
// baseline (speedup 1.0000x reference)
#include <cuda_runtime.h>
#include <math.h>

#define BATCH  2
#define SEQ    2048
#define DMODEL 1024
#define NH     16
#define HD     64
#define M_ROWS (BATCH * SEQ)    // 4096
#define QKV_N  (3 * DMODEL)     // 3072

// Scratch (device globals: no allocations allowed in kernel_launch)
__device__ float g_qkv[M_ROWS * QKV_N];            // [4096, 3072]
__device__ float g_q[BATCH * NH * SEQ * HD];       // [B,H,S,hd]
__device__ float g_k[BATCH * NH * SEQ * HD];
__device__ float g_v[BATCH * NH * SEQ * HD];
__device__ float g_attn[BATCH * NH * SEQ * HD];

// ---------------------------------------------------------------------------
// SGEMM: C[M,N] = A[M,K] @ B[K,N], fp32. BM=BN=128, BK=8, 256 threads, 8x8/thread.
// aAttn=1: A is g_attn in [B,H,S,hd] layout, logical A[m,k] with m=b*S+s, k=h*64+d.
// ---------------------------------------------------------------------------
__global__ void __launch_bounds__(256) sgemm_kernel(
    const float* __restrict__ A, const float* __restrict__ B,
    float* __restrict__ C, int M, int N, int K, int aAttn)
{
    __shared__ float As[8][128];
    __shared__ float Bs[8][128];

    const int bx = blockIdx.x;   // N tile
    const int by = blockIdx.y;   // M tile
    const int tid = threadIdx.x;
    const int tx = tid % 16;
    const int ty = tid / 16;

    // A tile load mapping: 128 rows x 8 cols, one float4 per thread
    const int aRow = tid >> 1;          // 0..127
    const int aCol = (tid & 1) * 4;     // 0 or 4
    // B tile load mapping: 8 rows x 128 cols, one float4 per thread
    const int bRow = tid >> 5;          // 0..7
    const int bCol = (tid & 31) * 4;    // 0..124

    float acc[8][8];
#pragma unroll
    for (int i = 0; i < 8; i++)
#pragma unroll
        for (int j = 0; j < 8; j++) acc[i][j] = 0.f;

    const int gRow = by * 128 + aRow;

    for (int k0 = 0; k0 < K; k0 += 8) {
        float4 a4;
        if (aAttn) {
            // m = b*2048 + s ; k = h*64 + d
            int b = gRow >> 11;
            int s = gRow & 2047;
            int kk = k0 + aCol;
            int h = kk >> 6;
            int d = kk & 63;
            a4 = *(const float4*)(A + (((size_t)(b * NH + h) * SEQ + s) * HD + d));
        } else {
            a4 = *(const float4*)(A + (size_t)gRow * K + k0 + aCol);
        }
        As[aCol + 0][aRow] = a4.x;
        As[aCol + 1][aRow] = a4.y;
        As[aCol + 2][aRow] = a4.z;
        As[aCol + 3][aRow] = a4.w;

        float4 b4 = *(const float4*)(B + (size_t)(k0 + bRow) * N + bx * 128 + bCol);
        *(float4*)&Bs[bRow][bCol] = b4;

        __syncthreads();

#pragma unroll
        for (int kk = 0; kk < 8; kk++) {
            float a[8], bb[8];
#pragma unroll
            for (int i = 0; i < 4; i++) {
                ((float4*)a)[0] = *(const float4*)&As[kk][ty * 8];
                ((float4*)a)[1] = *(const float4*)&As[kk][ty * 8 + 4];
                ((float4*)bb)[0] = *(const float4*)&Bs[kk][tx * 8];
                ((float4*)bb)[1] = *(const float4*)&Bs[kk][tx * 8 + 4];
                break;
            }
#pragma unroll
            for (int i = 0; i < 8; i++)
#pragma unroll
                for (int j = 0; j < 8; j++)
                    acc[i][j] += a[i] * bb[j];
        }
        __syncthreads();
    }

    // Write back (float4 stores)
#pragma unroll
    for (int i = 0; i < 8; i++) {
        size_t crow = (size_t)(by * 128 + ty * 8 + i) * N + bx * 128 + tx * 8;
        *(float4*)(C + crow)     = make_float4(acc[i][0], acc[i][1], acc[i][2], acc[i][3]);
        *(float4*)(C + crow + 4) = make_float4(acc[i][4], acc[i][5], acc[i][6], acc[i][7]);
    }
}

// ---------------------------------------------------------------------------
// RoPE + split + transpose: qkv[B,S,3D] -> q,k,v [B,H,S,hd] with RoPE on q,k.
// One thread per (b,h,s,j) pair, j in [0,32): handles dims j and j+32.
// ---------------------------------------------------------------------------
__global__ void rope_kernel(const float* __restrict__ qkv,
                            float* __restrict__ q, float* __restrict__ k,
                            float* __restrict__ v)
{
    int idx = blockIdx.x * blockDim.x + threadIdx.x;   // < B*NH*SEQ*32 = 2^21
    int j = idx & 31;
    int s = (idx >> 5) & 2047;
    int h = (idx >> 16) & 15;
    int b = idx >> 20;

    // inv_freq = 10000^(-j/32); accurate powf to track the f32 reference
    float inv_freq = powf(10000.0f, -(float)j * (1.0f / 32.0f));
    float ang = (float)s * inv_freq;
    float sn, cs;
    sincosf(ang, &sn, &cs);

    const float* src = qkv + ((size_t)(b * SEQ + s)) * QKV_N + h * HD;
    float q0 = src[j],          q1 = src[j + 32];
    float k0 = src[DMODEL + j], k1 = src[DMODEL + j + 32];

    size_t dst = ((size_t)((b * NH + h) * SEQ) + s) * HD;
    q[dst + j]      = q0 * cs - q1 * sn;
    q[dst + j + 32] = q1 * cs + q0 * sn;
    k[dst + j]      = k0 * cs - k1 * sn;
    k[dst + j + 32] = k1 * cs + k0 * sn;
    v[dst + j]      = src[2 * DMODEL + j];
    v[dst + j + 32] = src[2 * DMODEL + j + 32];
}

// ---------------------------------------------------------------------------
// Causal flash attention, fp32. Grid: (S/64, B*H). Block: 64 threads.
// Each thread owns one q row (q, o, partial scores in registers).
// K/V tiles (64x64) staged in padded smem; all smem reads are warp-broadcast.
// Online softmax per 16-key chunk keeps the score array fully unrolled.
// ---------------------------------------------------------------------------
__global__ void __launch_bounds__(64) attn_kernel(
    const float* __restrict__ Q, const float* __restrict__ K,
    const float* __restrict__ V, float* __restrict__ O)
{
    __shared__ float Ks[64][65];
    __shared__ float Vs[64][65];

    const int bh = blockIdx.y;
    const int qt = blockIdx.x;
    const int row = threadIdx.x;

    const size_t base = (size_t)bh * SEQ * HD;
    const float* Qp = Q + base + (size_t)(qt * 64 + row) * HD;

    float qreg[HD];
#pragma unroll
    for (int d = 0; d < HD; d++) qreg[d] = Qp[d] * 0.125f;   // 1/sqrt(64)

    float oacc[HD];
#pragma unroll
    for (int d = 0; d < HD; d++) oacc[d] = 0.f;
    float m = -INFINITY, l = 0.f;

    for (int kt = 0; kt <= qt; kt++) {
        const float4* Kg = (const float4*)(K + base + (size_t)kt * 64 * HD);
        const float4* Vg = (const float4*)(V + base + (size_t)kt * 64 * HD);
#pragma unroll
        for (int c = 0; c < 16; c++) {
            float4 kv = Kg[row * 16 + c];
            Ks[row][c * 4 + 0] = kv.x; Ks[row][c * 4 + 1] = kv.y;
            Ks[row][c * 4 + 2] = kv.z; Ks[row][c * 4 + 3] = kv.w;
            float4 vv = Vg[row * 16 + c];
            Vs[row][c * 4 + 0] = vv.x; Vs[row][c * 4 + 1] = vv.y;
            Vs[row][c * 4 + 2] = vv.z; Vs[row][c * 4 + 3] = vv.w;
        }
        __syncthreads();

        const bool diag = (kt == qt);

#pragma unroll 1
        for (int c0 = 0; c0 < 64; c0 += 16) {
            float s[16];
#pragma unroll
            for (int j = 0; j < 16; j++) {
                float a0 = 0.f, a1 = 0.f, a2 = 0.f, a3 = 0.f;
#pragma unroll
                for (int d = 0; d < HD; d += 4) {
                    a0 += qreg[d + 0] * Ks[c0 + j][d + 0];
                    a1 += qreg[d + 1] * Ks[c0 + j][d + 1];
                    a2 += qreg[d + 2] * Ks[c0 + j][d + 2];
                    a3 += qreg[d + 3] * Ks[c0 + j][d + 3];
                }
                float acc = (a0 + a1) + (a2 + a3);
                if (diag && (c0 + j) > row) acc = -INFINITY;
                s[j] = acc;
            }

            float mt = s[0];
#pragma unroll
            for (int j = 1; j < 16; j++) mt = fmaxf(mt, s[j]);
            float mnew = fmaxf(m, mt);
            float corr = __expf(m - mnew);   // m=-inf on first chunk -> corr=0
            m = mnew;
            l *= corr;
#pragma unroll
            for (int d = 0; d < HD; d++) oacc[d] *= corr;

#pragma unroll
            for (int j = 0; j < 16; j++) {
                float p = __expf(s[j] - m);  // masked: exp(-inf)=0
                l += p;
#pragma unroll
                for (int d = 0; d < HD; d++) oacc[d] += p * Vs[c0 + j][d];
            }
        }
        __syncthreads();
    }

    float inv = 1.0f / l;
    float* Op = O + base + (size_t)(qt * 64 + row) * HD;
#pragma unroll
    for (int d = 0; d < HD; d++) Op[d] = oacc[d] * inv;
}

// ---------------------------------------------------------------------------
extern "C" void kernel_launch(void* const* d_in, const int* in_sizes, int n_in,
                              void* d_out, int out_size)
{
    const float* x     = (const float*)d_in[0];   // [2, 2048, 1024]
    const float* w_qkv = (const float*)d_in[1];   // [1024, 3072]
    const float* w_out = (const float*)d_in[2];   // [1024, 1024]
    float* out = (float*)d_out;                   // [2, 2048, 1024]

    float *qkv, *q, *k, *v, *attn;
    cudaGetSymbolAddress((void**)&qkv,  g_qkv);
    cudaGetSymbolAddress((void**)&q,    g_q);
    cudaGetSymbolAddress((void**)&k,    g_k);
    cudaGetSymbolAddress((void**)&v,    g_v);
    cudaGetSymbolAddress((void**)&attn, g_attn);

    // 1) QKV projection: [4096,1024] @ [1024,3072]
    dim3 g1(QKV_N / 128, M_ROWS / 128);
    sgemm_kernel<<<g1, 256>>>(x, w_qkv, qkv, M_ROWS, QKV_N, DMODEL, 0);

    // 2) RoPE + split + transpose
    int rope_threads = BATCH * NH * SEQ * 32;     // 2^21
    rope_kernel<<<rope_threads / 256, 256>>>(qkv, q, k, v);

    // 3) Causal flash attention
    dim3 g3(SEQ / 64, BATCH * NH);
    attn_kernel<<<g3, 64>>>(q, k, v, attn);

    // 4) Output projection with fused transpose: [4096,1024] @ [1024,1024]
    dim3 g4(DMODEL / 128, M_ROWS / 128);
    sgemm_kernel<<<g4, 256>>>(attn, w_out, out, M_ROWS, DMODEL, DMODEL, 1);
}

// round 6
// speedup vs baseline: 1.0468x; 1.0468x over previous
#include <cuda_runtime.h>
#include <cuda_bf16.h>
#include <math.h>
#include <stdint.h>

#define BATCH  2
#define SEQ    2048
#define DMODEL 1024
#define NH     16
#define HD     64
#define M_ROWS (BATCH * SEQ)    // 4096
#define QKV_N  (3 * DMODEL)     // 3072

// ---------------------------------------------------------------------------
// Device scratch
// ---------------------------------------------------------------------------
__device__ float g_qkv[M_ROWS * QKV_N];
__device__ float g_q[BATCH * NH * SEQ * HD];
__device__ float g_k[BATCH * NH * SEQ * HD];
__device__ float g_v[BATCH * NH * SEQ * HD];
__device__ float g_attn[BATCH * NH * SEQ * HD];

__device__ __nv_bfloat16 g_xh[M_ROWS * DMODEL];
__device__ __nv_bfloat16 g_xl[M_ROWS * DMODEL];
__device__ __nv_bfloat16 g_wqh[QKV_N * DMODEL];   // [N,K] transposed
__device__ __nv_bfloat16 g_wql[QKV_N * DMODEL];
__device__ __nv_bfloat16 g_woh[DMODEL * DMODEL];  // [N,K] transposed
__device__ __nv_bfloat16 g_wol[DMODEL * DMODEL];
__device__ __nv_bfloat16 g_ah[M_ROWS * DMODEL];
__device__ __nv_bfloat16 g_al[M_ROWS * DMODEL];

// ---------------------------------------------------------------------------
// Baseline-PTX helpers (no sm_103a-gated features!)
// ---------------------------------------------------------------------------
__device__ __forceinline__ uint32_t smem_u32(const void* p) {
    uint32_t a;
    asm("{ .reg .u64 t; cvta.to.shared.u64 t, %1; cvt.u32.u64 %0, t; }"
        : "=r"(a) : "l"(p));
    return a;
}

#define CP_ASYNC_16(smem, gptr) \
    asm volatile("cp.async.cg.shared.global [%0], [%1], 16;\n" \
        :: "r"(smem), "l"(gptr))
#define CP_ASYNC_COMMIT() asm volatile("cp.async.commit_group;\n")
#define CP_ASYNC_WAIT(n)  asm volatile("cp.async.wait_group %0;\n" :: "n"(n))

__device__ __forceinline__ void ldsm_x4(uint32_t* r, uint32_t addr) {
    asm volatile("ldmatrix.sync.aligned.m8n8.x4.shared.b16 {%0,%1,%2,%3}, [%4];\n"
        : "=r"(r[0]), "=r"(r[1]), "=r"(r[2]), "=r"(r[3]) : "r"(addr));
}

// D(f32) += A(bf16) * B(bf16): m16n8k16
__device__ __forceinline__ void mma16816(float* d, const uint32_t* a, const uint32_t* b) {
    asm volatile(
        "mma.sync.aligned.m16n8k16.row.col.f32.bf16.bf16.f32 "
        "{%0,%1,%2,%3}, {%4,%5,%6,%7}, {%8,%9}, {%0,%1,%2,%3};\n"
        : "+f"(d[0]), "+f"(d[1]), "+f"(d[2]), "+f"(d[3])
        : "r"(a[0]), "r"(a[1]), "r"(a[2]), "r"(a[3]), "r"(b[0]), "r"(b[1]));
}

// ---------------------------------------------------------------------------
// fp32 -> (hi, lo) bf16 split helpers and conversion kernels
// ---------------------------------------------------------------------------
__device__ __forceinline__ void split2(float x, __nv_bfloat16& h, __nv_bfloat16& l) {
    h = __float2bfloat16(x);
    l = __float2bfloat16(x - __bfloat162float(h));
}

__global__ void convert_split_kernel(const float* __restrict__ src,
                                     __nv_bfloat16* __restrict__ hi,
                                     __nv_bfloat16* __restrict__ lo, int n) {
    int i = blockIdx.x * blockDim.x + threadIdx.x;
    if (i < n) split2(src[i], hi[i], lo[i]);
}

// W[K,N] fp32 -> WT[N,K] bf16 hi/lo (tiled transpose)
__global__ void transpose_split_kernel(const float* __restrict__ W,
                                       __nv_bfloat16* __restrict__ Thi,
                                       __nv_bfloat16* __restrict__ Tlo,
                                       int K, int N) {
    __shared__ float tile[32][33];
    int n = blockIdx.x * 32 + threadIdx.x;
    int k = blockIdx.y * 32 + threadIdx.y;
    tile[threadIdx.y][threadIdx.x] = W[(size_t)k * N + n];
    __syncthreads();
    int nt = blockIdx.x * 32 + threadIdx.y;
    int kt = blockIdx.y * 32 + threadIdx.x;
    float v = tile[threadIdx.x][threadIdx.y];
    __nv_bfloat16 h, l;
    split2(v, h, l);
    Thi[(size_t)nt * K + kt] = h;
    Tlo[(size_t)nt * K + kt] = l;
}

// attn [B,H,S,hd] fp32 -> [M=B*S, K=H*hd] bf16 hi/lo (fused transpose)
__global__ void convert_attn_kernel(const float* __restrict__ A,
                                    __nv_bfloat16* __restrict__ hi,
                                    __nv_bfloat16* __restrict__ lo) {
    int idx = blockIdx.x * blockDim.x + threadIdx.x;  // < 2^22
    int d = idx & 63;
    int s = (idx >> 6) & 2047;
    int h = (idx >> 17) & 15;
    int b = idx >> 21;
    float v = A[idx];
    int m = b * SEQ + s;
    int k = h * HD + d;
    __nv_bfloat16 bh, bl;
    split2(v, bh, bl);
    hi[(size_t)m * DMODEL + k] = bh;
    lo[(size_t)m * DMODEL + k] = bl;
}

// ---------------------------------------------------------------------------
// Tensor-core GEMM: C[M,N] = A[M,K] @ B[K,N] in emulated fp32 (bf16 x 3 terms).
// A: Ahi/Alo [M,K] row-major bf16. B: Bhi/Blo [N,K] (transposed, K-major).
// CTA 128x128, BK=32, 256 threads = 8 warps in 4(m) x 2(n), warp tile 32x64.
// cp.async double-buffered SMEM, 80B-padded rows (conflict-free ldmatrix).
// ---------------------------------------------------------------------------
#define G_BK 32
#define ROW_PITCH 80                    // 32 bf16 = 64B + 16B pad
#define TILE_BYTES (128 * ROW_PITCH)    // 10240
#define STAGE_BYTES (4 * TILE_BYTES)    // Ahi,Alo,Bhi,Blo
#define G_SMEM_BYTES (2 * STAGE_BYTES)  // 81920

__global__ void __launch_bounds__(256)
gemm_bf16x3_kernel(const __nv_bfloat16* __restrict__ Ahi,
                   const __nv_bfloat16* __restrict__ Alo,
                   const __nv_bfloat16* __restrict__ Bhi,
                   const __nv_bfloat16* __restrict__ Blo,
                   float* __restrict__ C, int M, int N, int K)
{
    extern __shared__ __align__(128) char dsm[];
    const uint32_t smem_base = smem_u32(dsm);

    const int tid = threadIdx.x;
    const int wid = tid >> 5;
    const int lane = tid & 31;
    const int warp_m = wid >> 1;       // 0..3  -> 32-row slice
    const int warp_n = wid & 1;        // 0..1  -> 64-col slice
    const int m0 = blockIdx.y * 128;
    const int n0 = blockIdx.x * 128;

    const __nv_bfloat16* gsrc[4] = {Ahi, Alo, Bhi, Blo};

    float acc[2][8][4];
#pragma unroll
    for (int i = 0; i < 2; i++)
#pragma unroll
        for (int j = 0; j < 8; j++)
#pragma unroll
            for (int c = 0; c < 4; c++) acc[i][j][c] = 0.f;

    const int nchunk = K / G_BK;

    // ---- async tile load: chunk ci -> stage (ci&1) ----
    auto issue = [&](int ci) {
        const int k0 = ci * G_BK;
        const uint32_t st = smem_base + (ci & 1) * STAGE_BYTES;
#pragma unroll
        for (int i = 0; i < 8; i++) {
            const int tile = i >> 1;                       // 0..3
            const int idx = ((i & 1) << 8) | tid;          // 0..511
            const int r = idx >> 2;                        // 0..127
            const int c = idx & 3;                         // 0..3 (16B chunks)
            const int grow = (tile < 2 ? m0 : n0) + r;
            const __nv_bfloat16* gp = gsrc[tile] + (size_t)grow * K + k0 + c * 8;
            CP_ASYNC_16(st + tile * TILE_BYTES + r * ROW_PITCH + c * 16, gp);
        }
        CP_ASYNC_COMMIT();
    };

    issue(0);

#pragma unroll 1
    for (int ci = 0; ci < nchunk; ci++) {
        if (ci + 1 < nchunk) issue(ci + 1);
        if (ci + 1 < nchunk) { CP_ASYNC_WAIT(1); } else { CP_ASYNC_WAIT(0); }
        __syncthreads();

        const uint32_t st = smem_base + (ci & 1) * STAGE_BYTES;
        const uint32_t sAhi = st;
        const uint32_t sAlo = st + TILE_BYTES;
        const uint32_t sBhi = st + 2 * TILE_BYTES;
        const uint32_t sBlo = st + 3 * TILE_BYTES;

        // ldmatrix address offsets for this thread
        const int a_row_off = (lane & 15);                 // within 16-row tile
        const int a_k_off   = ((lane >> 4) & 1) * 8;       // 0 or 8
        const int b_row_off = ((lane & 16) >> 1) + (lane & 7);  // +8 for t>=16
        const int b_k_off   = (lane & 8);                  // 0 or 8

#pragma unroll
        for (int ks = 0; ks < 2; ks++) {
            uint32_t ahi[2][4], alo[2][4];
#pragma unroll
            for (int mt = 0; mt < 2; mt++) {
                const uint32_t aoff =
                    (uint32_t)((warp_m * 32 + mt * 16 + a_row_off) * ROW_PITCH +
                               (ks * 16 + a_k_off) * 2);
                ldsm_x4(ahi[mt], sAhi + aoff);
                ldsm_x4(alo[mt], sAlo + aoff);
            }
#pragma unroll
            for (int ntp = 0; ntp < 4; ntp++) {
                const uint32_t boff =
                    (uint32_t)((warp_n * 64 + ntp * 16 + b_row_off) * ROW_PITCH +
                               (ks * 16 + b_k_off) * 2);
                uint32_t bh4[4], bl4[4];
                ldsm_x4(bh4, sBhi + boff);
                ldsm_x4(bl4, sBlo + boff);
#pragma unroll
                for (int mt = 0; mt < 2; mt++)
#pragma unroll
                    for (int j = 0; j < 2; j++) {
                        float* d = acc[mt][2 * ntp + j];
                        mma16816(d, ahi[mt], &bh4[2 * j]);
                        mma16816(d, ahi[mt], &bl4[2 * j]);
                        mma16816(d, alo[mt], &bh4[2 * j]);
                    }
            }
        }
        __syncthreads();
    }

    // ---- epilogue ----
    const int quad = lane >> 2;
    const int tq = lane & 3;
    float* Cw = C + (size_t)(m0 + warp_m * 32) * N + n0 + warp_n * 64;
#pragma unroll
    for (int mt = 0; mt < 2; mt++)
#pragma unroll
        for (int nt = 0; nt < 8; nt++) {
            const int r = mt * 16 + quad;
            const int c = nt * 8 + tq * 2;
            *(float2*)(Cw + (size_t)r * N + c) =
                make_float2(acc[mt][nt][0], acc[mt][nt][1]);
            *(float2*)(Cw + (size_t)(r + 8) * N + c) =
                make_float2(acc[mt][nt][2], acc[mt][nt][3]);
        }
}

// ---------------------------------------------------------------------------
// RoPE + split + transpose
// ---------------------------------------------------------------------------
__global__ void rope_kernel(const float* __restrict__ qkv,
                            float* __restrict__ q, float* __restrict__ k,
                            float* __restrict__ v)
{
    int idx = blockIdx.x * blockDim.x + threadIdx.x;
    int j = idx & 31;
    int s = (idx >> 5) & 2047;
    int h = (idx >> 16) & 15;
    int b = idx >> 20;

    float inv_freq = powf(10000.0f, -(float)j * (1.0f / 32.0f));
    float ang = (float)s * inv_freq;
    float sn, cs;
    sincosf(ang, &sn, &cs);

    const float* src = qkv + ((size_t)(b * SEQ + s)) * QKV_N + h * HD;
    float q0 = src[j],          q1 = src[j + 32];
    float k0 = src[DMODEL + j], k1 = src[DMODEL + j + 32];

    size_t dst = ((size_t)((b * NH + h) * SEQ) + s) * HD;
    q[dst + j]      = q0 * cs - q1 * sn;
    q[dst + j + 32] = q1 * cs + q0 * sn;
    k[dst + j]      = k0 * cs - k1 * sn;
    k[dst + j + 32] = k1 * cs + k0 * sn;
    v[dst + j]      = src[2 * DMODEL + j];
    v[dst + j + 32] = src[2 * DMODEL + j + 32];
}

// ---------------------------------------------------------------------------
// Causal flash attention, fp32. 128 threads: 2 threads per q-row.
// ---------------------------------------------------------------------------
__global__ void __launch_bounds__(128) attn_kernel(
    const float* __restrict__ Q, const float* __restrict__ K,
    const float* __restrict__ V, float* __restrict__ O)
{
    __shared__ float Ks[64][65];
    __shared__ float Vs[64][65];

    const int bh = blockIdx.y;
    const int qt = blockIdx.x;
    const int t = threadIdx.x;
    const int row = t >> 1;
    const int h = t & 1;

    const size_t base = (size_t)bh * SEQ * HD;
    const float* Qp = Q + base + (size_t)(qt * 64 + row) * HD + h * 32;

    float qreg[32];
#pragma unroll
    for (int d = 0; d < 32; d++) qreg[d] = Qp[d] * 0.125f;  // 1/sqrt(64)

    float oacc[32];
#pragma unroll
    for (int d = 0; d < 32; d++) oacc[d] = 0.f;
    float m = -INFINITY, l = 0.f;

    for (int kt = 0; kt <= qt; kt++) {
        const float4* Kg = (const float4*)(K + base + (size_t)kt * 64 * HD);
        const float4* Vg = (const float4*)(V + base + (size_t)kt * 64 * HD);
#pragma unroll
        for (int c = 0; c < 8; c++) {
            int fi = row * 16 + h * 8 + c;
            float4 kv = Kg[fi];
            Ks[row][h * 32 + c * 4 + 0] = kv.x; Ks[row][h * 32 + c * 4 + 1] = kv.y;
            Ks[row][h * 32 + c * 4 + 2] = kv.z; Ks[row][h * 32 + c * 4 + 3] = kv.w;
            float4 vv = Vg[fi];
            Vs[row][h * 32 + c * 4 + 0] = vv.x; Vs[row][h * 32 + c * 4 + 1] = vv.y;
            Vs[row][h * 32 + c * 4 + 2] = vv.z; Vs[row][h * 32 + c * 4 + 3] = vv.w;
        }
        __syncthreads();

        const bool diag = (kt == qt);

#pragma unroll 1
        for (int c0 = 0; c0 < 64; c0 += 16) {
            float s[16];
#pragma unroll
            for (int j = 0; j < 16; j++) {
                float a0 = 0.f, a1 = 0.f, a2 = 0.f, a3 = 0.f;
                const float* kr = &Ks[c0 + j][h * 32];
#pragma unroll
                for (int d = 0; d < 32; d += 4) {
                    a0 += qreg[d + 0] * kr[d + 0];
                    a1 += qreg[d + 1] * kr[d + 1];
                    a2 += qreg[d + 2] * kr[d + 2];
                    a3 += qreg[d + 3] * kr[d + 3];
                }
                float acc = (a0 + a1) + (a2 + a3);
                acc += __shfl_xor_sync(0xffffffffu, acc, 1);
                if (diag && (c0 + j) > row) acc = -INFINITY;
                s[j] = acc;
            }

            float mt = s[0];
#pragma unroll
            for (int j = 1; j < 16; j++) mt = fmaxf(mt, s[j]);
            float mnew = fmaxf(m, mt);
            float corr = __expf(m - mnew);
            m = mnew;
            l *= corr;
#pragma unroll
            for (int d = 0; d < 32; d++) oacc[d] *= corr;

#pragma unroll
            for (int j = 0; j < 16; j++) {
                float p = __expf(s[j] - m);
                l += p;
                const float* vr = &Vs[c0 + j][h * 32];
#pragma unroll
                for (int d = 0; d < 32; d++) oacc[d] += p * vr[d];
            }
        }
        __syncthreads();
    }

    float inv = 1.0f / l;
    float* Op = O + base + (size_t)(qt * 64 + row) * HD + h * 32;
#pragma unroll
    for (int d = 0; d < 32; d++) Op[d] = oacc[d] * inv;
}

// ---------------------------------------------------------------------------
extern "C" void kernel_launch(void* const* d_in, const int* in_sizes, int n_in,
                              void* d_out, int out_size)
{
    const float* x     = (const float*)d_in[0];
    const float* w_qkv = (const float*)d_in[1];
    const float* w_out = (const float*)d_in[2];
    float* out = (float*)d_out;

    float *qkv, *q, *k, *v, *attn;
    cudaGetSymbolAddress((void**)&qkv,  g_qkv);
    cudaGetSymbolAddress((void**)&q,    g_q);
    cudaGetSymbolAddress((void**)&k,    g_k);
    cudaGetSymbolAddress((void**)&v,    g_v);
    cudaGetSymbolAddress((void**)&attn, g_attn);

    __nv_bfloat16 *xh, *xl, *wqh, *wql, *woh, *wol, *ah, *al;
    cudaGetSymbolAddress((void**)&xh,  g_xh);
    cudaGetSymbolAddress((void**)&xl,  g_xl);
    cudaGetSymbolAddress((void**)&wqh, g_wqh);
    cudaGetSymbolAddress((void**)&wql, g_wql);
    cudaGetSymbolAddress((void**)&woh, g_woh);
    cudaGetSymbolAddress((void**)&wol, g_wol);
    cudaGetSymbolAddress((void**)&ah,  g_ah);
    cudaGetSymbolAddress((void**)&al,  g_al);

    cudaFuncSetAttribute(gemm_bf16x3_kernel,
                         cudaFuncAttributeMaxDynamicSharedMemorySize, G_SMEM_BYTES);

    // 1) Convert inputs to split-bf16
    {
        int n = M_ROWS * DMODEL;
        convert_split_kernel<<<(n + 255) / 256, 256>>>(x, xh, xl, n);
    }
    transpose_split_kernel<<<dim3(QKV_N / 32, DMODEL / 32), dim3(32, 32)>>>(
        w_qkv, wqh, wql, DMODEL, QKV_N);
    transpose_split_kernel<<<dim3(DMODEL / 32, DMODEL / 32), dim3(32, 32)>>>(
        w_out, woh, wol, DMODEL, DMODEL);

    // 2) QKV projection on tensor cores: [4096,1024] @ [1024,3072]
    gemm_bf16x3_kernel<<<dim3(QKV_N / 128, M_ROWS / 128), 256, G_SMEM_BYTES>>>(
        xh, xl, wqh, wql, qkv, M_ROWS, QKV_N, DMODEL);

    // 3) RoPE + split + transpose
    rope_kernel<<<(BATCH * NH * SEQ * 32) / 256, 256>>>(qkv, q, k, v);

    // 4) Causal flash attention
    attn_kernel<<<dim3(SEQ / 64, BATCH * NH), 128>>>(q, k, v, attn);

    // 5) Convert attention output (fused transpose) + output projection
    {
        int n = M_ROWS * DMODEL;
        convert_attn_kernel<<<(n + 255) / 256, 256>>>(attn, ah, al);
    }
    gemm_bf16x3_kernel<<<dim3(DMODEL / 128, M_ROWS / 128), 256, G_SMEM_BYTES>>>(
        ah, al, woh, wol, out, M_ROWS, DMODEL, DMODEL);
}

// round 7
// speedup vs baseline: 3.4247x; 3.2715x over previous
#include <cuda_runtime.h>
#include <cuda_bf16.h>
#include <math.h>
#include <stdint.h>

#define BATCH  2
#define SEQ    2048
#define DMODEL 1024
#define NH     16
#define HD     64
#define M_ROWS (BATCH * SEQ)    // 4096
#define QKV_N  (3 * DMODEL)     // 3072

// ---------------------------------------------------------------------------
// Device scratch
// ---------------------------------------------------------------------------
__device__ float g_qkv[M_ROWS * QKV_N];

__device__ __nv_bfloat16 g_xh[M_ROWS * DMODEL];
__device__ __nv_bfloat16 g_xl[M_ROWS * DMODEL];
__device__ __nv_bfloat16 g_wqh[QKV_N * DMODEL];   // [N,K] transposed
__device__ __nv_bfloat16 g_wql[QKV_N * DMODEL];
__device__ __nv_bfloat16 g_woh[DMODEL * DMODEL];  // [N,K] transposed
__device__ __nv_bfloat16 g_wol[DMODEL * DMODEL];
__device__ __nv_bfloat16 g_ah[M_ROWS * DMODEL];   // attention out hi (A of out-proj)
__device__ __nv_bfloat16 g_al[M_ROWS * DMODEL];

#define QKV_ELEMS (BATCH * NH * SEQ * HD)
__device__ __nv_bfloat16 g_qh[QKV_ELEMS];  // [B,H,S,hd], pre-scaled by 1/8
__device__ __nv_bfloat16 g_ql[QKV_ELEMS];
__device__ __nv_bfloat16 g_kh[QKV_ELEMS];
__device__ __nv_bfloat16 g_kl[QKV_ELEMS];
__device__ __nv_bfloat16 g_vh[QKV_ELEMS];
__device__ __nv_bfloat16 g_vl[QKV_ELEMS];

// ---------------------------------------------------------------------------
// Baseline-PTX helpers (no sm_103a-gated features)
// ---------------------------------------------------------------------------
__device__ __forceinline__ uint32_t smem_u32(const void* p) {
    uint32_t a;
    asm("{ .reg .u64 t; cvta.to.shared.u64 t, %1; cvt.u32.u64 %0, t; }"
        : "=r"(a) : "l"(p));
    return a;
}

#define CP_ASYNC_16(smem, gptr) \
    asm volatile("cp.async.cg.shared.global [%0], [%1], 16;\n" \
        :: "r"(smem), "l"(gptr))
#define CP_ASYNC_COMMIT() asm volatile("cp.async.commit_group;\n")
#define CP_ASYNC_WAIT(n)  asm volatile("cp.async.wait_group %0;\n" :: "n"(n))

__device__ __forceinline__ void ldsm_x4(uint32_t* r, uint32_t addr) {
    asm volatile("ldmatrix.sync.aligned.m8n8.x4.shared.b16 {%0,%1,%2,%3}, [%4];\n"
        : "=r"(r[0]), "=r"(r[1]), "=r"(r[2]), "=r"(r[3]) : "r"(addr));
}
__device__ __forceinline__ void ldsm_x4_t(uint32_t* r, uint32_t addr) {
    asm volatile("ldmatrix.sync.aligned.m8n8.x4.trans.shared.b16 {%0,%1,%2,%3}, [%4];\n"
        : "=r"(r[0]), "=r"(r[1]), "=r"(r[2]), "=r"(r[3]) : "r"(addr));
}

// D(f32) += A(bf16) * B(bf16): m16n8k16
__device__ __forceinline__ void mma16816(float* d, const uint32_t* a, const uint32_t* b) {
    asm volatile(
        "mma.sync.aligned.m16n8k16.row.col.f32.bf16.bf16.f32 "
        "{%0,%1,%2,%3}, {%4,%5,%6,%7}, {%8,%9}, {%0,%1,%2,%3};\n"
        : "+f"(d[0]), "+f"(d[1]), "+f"(d[2]), "+f"(d[3])
        : "r"(a[0]), "r"(a[1]), "r"(a[2]), "r"(a[3]), "r"(b[0]), "r"(b[1]));
}

// ---------------------------------------------------------------------------
// fp32 -> (hi, lo) bf16 split helpers
// ---------------------------------------------------------------------------
__device__ __forceinline__ void split2(float x, __nv_bfloat16& h, __nv_bfloat16& l) {
    h = __float2bfloat16(x);
    l = __float2bfloat16(x - __bfloat162float(h));
}
__device__ __forceinline__ uint32_t pack_bf2(__nv_bfloat16 a, __nv_bfloat16 b) {
    __nv_bfloat162 t; t.x = a; t.y = b;
    return *(uint32_t*)&t;
}

__global__ void convert_split_kernel(const float* __restrict__ src,
                                     __nv_bfloat16* __restrict__ hi,
                                     __nv_bfloat16* __restrict__ lo, int n) {
    int i = blockIdx.x * blockDim.x + threadIdx.x;
    if (i < n) split2(src[i], hi[i], lo[i]);
}

// W[K,N] fp32 -> WT[N,K] bf16 hi/lo (tiled transpose)
__global__ void transpose_split_kernel(const float* __restrict__ W,
                                       __nv_bfloat16* __restrict__ Thi,
                                       __nv_bfloat16* __restrict__ Tlo,
                                       int K, int N) {
    __shared__ float tile[32][33];
    int n = blockIdx.x * 32 + threadIdx.x;
    int k = blockIdx.y * 32 + threadIdx.y;
    tile[threadIdx.y][threadIdx.x] = W[(size_t)k * N + n];
    __syncthreads();
    int nt = blockIdx.x * 32 + threadIdx.y;
    int kt = blockIdx.y * 32 + threadIdx.x;
    float v = tile[threadIdx.x][threadIdx.y];
    __nv_bfloat16 h, l;
    split2(v, h, l);
    Thi[(size_t)nt * K + kt] = h;
    Tlo[(size_t)nt * K + kt] = l;
}

// ---------------------------------------------------------------------------
// Tensor-core GEMM (same as R5): C = A@B, bf16 x 3-term fp32 emulation.
// ---------------------------------------------------------------------------
#define G_BK 32
#define ROW_PITCH 80
#define TILE_BYTES (128 * ROW_PITCH)
#define STAGE_BYTES (4 * TILE_BYTES)
#define G_SMEM_BYTES (2 * STAGE_BYTES)

__global__ void __launch_bounds__(256)
gemm_bf16x3_kernel(const __nv_bfloat16* __restrict__ Ahi,
                   const __nv_bfloat16* __restrict__ Alo,
                   const __nv_bfloat16* __restrict__ Bhi,
                   const __nv_bfloat16* __restrict__ Blo,
                   float* __restrict__ C, int M, int N, int K)
{
    extern __shared__ __align__(128) char dsm[];
    const uint32_t smem_base = smem_u32(dsm);

    const int tid = threadIdx.x;
    const int wid = tid >> 5;
    const int lane = tid & 31;
    const int warp_m = wid >> 1;
    const int warp_n = wid & 1;
    const int m0 = blockIdx.y * 128;
    const int n0 = blockIdx.x * 128;

    const __nv_bfloat16* gsrc[4] = {Ahi, Alo, Bhi, Blo};

    float acc[2][8][4];
#pragma unroll
    for (int i = 0; i < 2; i++)
#pragma unroll
        for (int j = 0; j < 8; j++)
#pragma unroll
            for (int c = 0; c < 4; c++) acc[i][j][c] = 0.f;

    const int nchunk = K / G_BK;

    auto issue = [&](int ci) {
        const int k0 = ci * G_BK;
        const uint32_t st = smem_base + (ci & 1) * STAGE_BYTES;
#pragma unroll
        for (int i = 0; i < 8; i++) {
            const int tile = i >> 1;
            const int idx = ((i & 1) << 8) | tid;
            const int r = idx >> 2;
            const int c = idx & 3;
            const int grow = (tile < 2 ? m0 : n0) + r;
            const __nv_bfloat16* gp = gsrc[tile] + (size_t)grow * K + k0 + c * 8;
            CP_ASYNC_16(st + tile * TILE_BYTES + r * ROW_PITCH + c * 16, gp);
        }
        CP_ASYNC_COMMIT();
    };

    issue(0);

#pragma unroll 1
    for (int ci = 0; ci < nchunk; ci++) {
        if (ci + 1 < nchunk) { issue(ci + 1); CP_ASYNC_WAIT(1); }
        else                 { CP_ASYNC_WAIT(0); }
        __syncthreads();

        const uint32_t st = smem_base + (ci & 1) * STAGE_BYTES;
        const uint32_t sAhi = st;
        const uint32_t sAlo = st + TILE_BYTES;
        const uint32_t sBhi = st + 2 * TILE_BYTES;
        const uint32_t sBlo = st + 3 * TILE_BYTES;

        const int a_row_off = (lane & 15);
        const int a_k_off   = ((lane >> 4) & 1) * 8;
        const int b_row_off = ((lane & 16) >> 1) + (lane & 7);
        const int b_k_off   = (lane & 8);

#pragma unroll
        for (int ks = 0; ks < 2; ks++) {
            uint32_t ahi[2][4], alo[2][4];
#pragma unroll
            for (int mt = 0; mt < 2; mt++) {
                const uint32_t aoff =
                    (uint32_t)((warp_m * 32 + mt * 16 + a_row_off) * ROW_PITCH +
                               (ks * 16 + a_k_off) * 2);
                ldsm_x4(ahi[mt], sAhi + aoff);
                ldsm_x4(alo[mt], sAlo + aoff);
            }
#pragma unroll
            for (int ntp = 0; ntp < 4; ntp++) {
                const uint32_t boff =
                    (uint32_t)((warp_n * 64 + ntp * 16 + b_row_off) * ROW_PITCH +
                               (ks * 16 + b_k_off) * 2);
                uint32_t bh4[4], bl4[4];
                ldsm_x4(bh4, sBhi + boff);
                ldsm_x4(bl4, sBlo + boff);
#pragma unroll
                for (int mt = 0; mt < 2; mt++)
#pragma unroll
                    for (int j = 0; j < 2; j++) {
                        float* d = acc[mt][2 * ntp + j];
                        mma16816(d, ahi[mt], &bh4[2 * j]);
                        mma16816(d, ahi[mt], &bl4[2 * j]);
                        mma16816(d, alo[mt], &bh4[2 * j]);
                    }
            }
        }
        __syncthreads();
    }

    const int quad = lane >> 2;
    const int tq = lane & 3;
    float* Cw = C + (size_t)(m0 + warp_m * 32) * N + n0 + warp_n * 64;
#pragma unroll
    for (int mt = 0; mt < 2; mt++)
#pragma unroll
        for (int nt = 0; nt < 8; nt++) {
            const int r = mt * 16 + quad;
            const int c = nt * 8 + tq * 2;
            *(float2*)(Cw + (size_t)r * N + c) =
                make_float2(acc[mt][nt][0], acc[mt][nt][1]);
            *(float2*)(Cw + (size_t)(r + 8) * N + c) =
                make_float2(acc[mt][nt][2], acc[mt][nt][3]);
        }
}

// ---------------------------------------------------------------------------
// RoPE + split into bf16 hi/lo. q pre-scaled by 1/8 (softmax scale).
// Outputs q,k,v in [B,H,S,hd] bf16 hi/lo.
// ---------------------------------------------------------------------------
__global__ void rope_split_kernel(const float* __restrict__ qkv,
                                  __nv_bfloat16* __restrict__ qh, __nv_bfloat16* __restrict__ ql,
                                  __nv_bfloat16* __restrict__ kh, __nv_bfloat16* __restrict__ kl,
                                  __nv_bfloat16* __restrict__ vh, __nv_bfloat16* __restrict__ vl)
{
    int idx = blockIdx.x * blockDim.x + threadIdx.x;   // < 2^21
    int j = idx & 31;
    int s = (idx >> 5) & 2047;
    int h = (idx >> 16) & 15;
    int b = idx >> 20;

    float inv_freq = powf(10000.0f, -(float)j * (1.0f / 32.0f));
    float ang = (float)s * inv_freq;
    float sn, cs;
    sincosf(ang, &sn, &cs);

    const float* src = qkv + ((size_t)(b * SEQ + s)) * QKV_N + h * HD;
    float q0 = src[j],          q1 = src[j + 32];
    float k0 = src[DMODEL + j], k1 = src[DMODEL + j + 32];
    float v0 = src[2 * DMODEL + j], v1 = src[2 * DMODEL + j + 32];

    float qa = (q0 * cs - q1 * sn) * 0.125f;
    float qb = (q1 * cs + q0 * sn) * 0.125f;
    float ka = k0 * cs - k1 * sn;
    float kb = k1 * cs + k0 * sn;

    size_t dst = ((size_t)((b * NH + h) * SEQ) + s) * HD;
    __nv_bfloat16 hh, ll;
    split2(qa, hh, ll); qh[dst + j] = hh;      ql[dst + j] = ll;
    split2(qb, hh, ll); qh[dst + j + 32] = hh; ql[dst + j + 32] = ll;
    split2(ka, hh, ll); kh[dst + j] = hh;      kl[dst + j] = ll;
    split2(kb, hh, ll); kh[dst + j + 32] = hh; kl[dst + j + 32] = ll;
    split2(v0, hh, ll); vh[dst + j] = hh;      vl[dst + j] = ll;
    split2(v1, hh, ll); vh[dst + j + 32] = hh; vl[dst + j + 32] = ll;
}

// ---------------------------------------------------------------------------
// Tensor-core causal flash attention (bf16 x 3-term emulation).
// Block: 128 threads = 4 warps, 64 q-rows (16/warp). Key tiles of 64.
// K/V hi/lo tiles in smem (144B pitch, conflict-free ldmatrix), double-buffer.
// Output written as split-bf16 directly into out-proj A layout [B*S, H*hd].
// ---------------------------------------------------------------------------
#define AT_PITCH_B 144                    // 72 bf16 per row
#define AT_TILE_B  (64 * AT_PITCH_B)      // 9216
#define AT_STAGE_B (4 * AT_TILE_B)        // 36864
#define AT_SMEM_B  (2 * AT_STAGE_B)       // 73728

__global__ void __launch_bounds__(128)
attn_tc_kernel(const __nv_bfloat16* __restrict__ qh, const __nv_bfloat16* __restrict__ ql,
               const __nv_bfloat16* __restrict__ kh, const __nv_bfloat16* __restrict__ kl,
               const __nv_bfloat16* __restrict__ vh, const __nv_bfloat16* __restrict__ vl,
               __nv_bfloat16* __restrict__ outh, __nv_bfloat16* __restrict__ outl)
{
    extern __shared__ __align__(128) char dsm[];
    const uint32_t sb = smem_u32(dsm);

    const int bh = blockIdx.y;
    const int qt = gridDim.x - 1 - blockIdx.x;   // heavy tiles first
    const int tid = threadIdx.x;
    const int wid = tid >> 5;
    const int lane = tid & 31;
    const int kq = (lane & 3) * 2;               // fragment col offset
    const size_t base = (size_t)bh * SEQ * HD;

    const __nv_bfloat16* khp = kh + base;
    const __nv_bfloat16* klp = kl + base;
    const __nv_bfloat16* vhp = vh + base;
    const __nv_bfloat16* vlp = vl + base;

    // ---- Q fragments (register resident) ----
    const int rloc = wid * 16 + (lane >> 2);     // local q row (0..63), +8 pair
    const int grow = qt * 64 + rloc;
    uint32_t qfh[4][4], qfl[4][4];
#pragma unroll
    for (int kc = 0; kc < 4; kc++) {
        size_t o = base + (size_t)grow * HD + kc * 16 + kq;
        qfh[kc][0] = *(const uint32_t*)(qh + o);
        qfh[kc][1] = *(const uint32_t*)(qh + o + 8 * HD);
        qfh[kc][2] = *(const uint32_t*)(qh + o + 8);
        qfh[kc][3] = *(const uint32_t*)(qh + o + 8 * HD + 8);
        qfl[kc][0] = *(const uint32_t*)(ql + o);
        qfl[kc][1] = *(const uint32_t*)(ql + o + 8 * HD);
        qfl[kc][2] = *(const uint32_t*)(ql + o + 8);
        qfl[kc][3] = *(const uint32_t*)(ql + o + 8 * HD + 8);
    }

    float oa[8][4];
#pragma unroll
    for (int i = 0; i < 8; i++)
#pragma unroll
        for (int c = 0; c < 4; c++) oa[i][c] = 0.f;
    float m0 = -INFINITY, m1 = -INFINITY, l0 = 0.f, l1 = 0.f;

    auto issue = [&](int kt) {
        const uint32_t st = sb + (kt & 1) * AT_STAGE_B;
        const __nv_bfloat16* srcs[4] = {khp, klp, vhp, vlp};
        const int kr0 = kt * 64;
#pragma unroll
        for (int t = 0; t < 4; t++) {
#pragma unroll
            for (int i = 0; i < 4; i++) {
                int c = i * 128 + tid;           // 0..511
                int row = c >> 3, col = c & 7;
                CP_ASYNC_16(st + t * AT_TILE_B + row * AT_PITCH_B + col * 16,
                            srcs[t] + (size_t)(kr0 + row) * HD + col * 8);
            }
        }
        CP_ASYNC_COMMIT();
    };

    issue(0);

    const int b_row = ((lane & 16) >> 1) + (lane & 7);
    const int b_k   = (lane & 8);
    const int vg    = lane >> 3;                 // 0..3 for trans-ldmatrix groups

#pragma unroll 1
    for (int kt = 0; kt <= qt; kt++) {
        if (kt < qt) { issue(kt + 1); CP_ASYNC_WAIT(1); }
        else         { CP_ASYNC_WAIT(0); }
        __syncthreads();

        const uint32_t st  = sb + (kt & 1) * AT_STAGE_B;
        const uint32_t sKh = st;
        const uint32_t sKl = st + AT_TILE_B;
        const uint32_t sVh = st + 2 * AT_TILE_B;
        const uint32_t sVl = st + 3 * AT_TILE_B;

        // ---- S = Q @ K^T (3-term) ----
        float sacc[8][4];
#pragma unroll
        for (int i = 0; i < 8; i++)
#pragma unroll
            for (int c = 0; c < 4; c++) sacc[i][c] = 0.f;

#pragma unroll
        for (int kc = 0; kc < 4; kc++) {
#pragma unroll
            for (int np = 0; np < 4; np++) {
                const uint32_t addr = (uint32_t)((np * 16 + b_row) * AT_PITCH_B +
                                                 (kc * 16 + b_k) * 2);
                uint32_t bh4[4], bl4[4];
                ldsm_x4(bh4, sKh + addr);
                ldsm_x4(bl4, sKl + addr);
#pragma unroll
                for (int j = 0; j < 2; j++) {
                    float* d = sacc[2 * np + j];
                    mma16816(d, qfh[kc], &bh4[2 * j]);
                    mma16816(d, qfh[kc], &bl4[2 * j]);
                    mma16816(d, qfl[kc], &bh4[2 * j]);
                }
            }
        }

        // ---- causal mask on the diagonal tile ----
        if (kt == qt) {
#pragma unroll
            for (int nt = 0; nt < 8; nt++) {
                int col = nt * 8 + kq;
                if (col > rloc)      sacc[nt][0] = -INFINITY;
                if (col + 1 > rloc)  sacc[nt][1] = -INFINITY;
                if (col > rloc + 8)      sacc[nt][2] = -INFINITY;
                if (col + 1 > rloc + 8)  sacc[nt][3] = -INFINITY;
            }
        }

        // ---- online softmax (fragment layout) ----
        float rm0 = -INFINITY, rm1 = -INFINITY;
#pragma unroll
        for (int nt = 0; nt < 8; nt++) {
            rm0 = fmaxf(rm0, fmaxf(sacc[nt][0], sacc[nt][1]));
            rm1 = fmaxf(rm1, fmaxf(sacc[nt][2], sacc[nt][3]));
        }
        rm0 = fmaxf(rm0, __shfl_xor_sync(0xffffffffu, rm0, 1));
        rm0 = fmaxf(rm0, __shfl_xor_sync(0xffffffffu, rm0, 2));
        rm1 = fmaxf(rm1, __shfl_xor_sync(0xffffffffu, rm1, 1));
        rm1 = fmaxf(rm1, __shfl_xor_sync(0xffffffffu, rm1, 2));

        float mn0 = fmaxf(m0, rm0), mn1 = fmaxf(m1, rm1);
        float c0 = __expf(m0 - mn0), c1 = __expf(m1 - mn1);
        m0 = mn0; m1 = mn1;
        l0 *= c0; l1 *= c1;
#pragma unroll
        for (int nt = 0; nt < 8; nt++) {
            oa[nt][0] *= c0; oa[nt][1] *= c0;
            oa[nt][2] *= c1; oa[nt][3] *= c1;
        }

        // ---- P = exp(S - m), split + repack into A fragments ----
        uint32_t pfh[4][4], pfl[4][4];
        float ps0 = 0.f, ps1 = 0.f;
#pragma unroll
        for (int np = 0; np < 4; np++) {
#pragma unroll
            for (int j = 0; j < 2; j++) {
                const int t = 2 * np + j;
                float p0 = __expf(sacc[t][0] - m0);
                float p1 = __expf(sacc[t][1] - m0);
                float p2 = __expf(sacc[t][2] - m1);
                float p3 = __expf(sacc[t][3] - m1);
                ps0 += p0 + p1; ps1 += p2 + p3;
                __nv_bfloat16 h0, e0, h1, e1, h2, e2, h3, e3;
                split2(p0, h0, e0); split2(p1, h1, e1);
                split2(p2, h2, e2); split2(p3, h3, e3);
                pfh[np][2 * j]     = pack_bf2(h0, h1);
                pfh[np][2 * j + 1] = pack_bf2(h2, h3);
                pfl[np][2 * j]     = pack_bf2(e0, e1);
                pfl[np][2 * j + 1] = pack_bf2(e2, e3);
            }
        }
        ps0 += __shfl_xor_sync(0xffffffffu, ps0, 1);
        ps0 += __shfl_xor_sync(0xffffffffu, ps0, 2);
        ps1 += __shfl_xor_sync(0xffffffffu, ps1, 1);
        ps1 += __shfl_xor_sync(0xffffffffu, ps1, 2);
        l0 += ps0; l1 += ps1;

        // ---- O += P @ V (3-term), V^T fragments via ldmatrix.trans ----
#pragma unroll
        for (int kc2 = 0; kc2 < 4; kc2++) {
#pragma unroll
            for (int dp = 0; dp < 4; dp++) {
                const int vrow = kc2 * 16 + (lane & 7) + (vg & 1) * 8;
                const int vcol = dp * 16 + (vg >> 1) * 8;
                const uint32_t addr = (uint32_t)(vrow * AT_PITCH_B + vcol * 2);
                uint32_t bvh[4], bvl[4];
                ldsm_x4_t(bvh, sVh + addr);
                ldsm_x4_t(bvl, sVl + addr);
#pragma unroll
                for (int j = 0; j < 2; j++) {
                    float* d = oa[2 * dp + j];
                    mma16816(d, pfh[kc2], &bvh[2 * j]);
                    mma16816(d, pfl[kc2], &bvh[2 * j]);
                    mma16816(d, pfh[kc2], &bvl[2 * j]);
                }
            }
        }
        __syncthreads();
    }

    // ---- epilogue: normalize, split, write [B*S, H*hd] bf16 hi/lo ----
    const float il0 = 1.0f / l0, il1 = 1.0f / l1;
    const int b = bh >> 4, h = bh & 15;
    const int s0 = qt * 64 + wid * 16 + (lane >> 2);
    const size_t mrow0 = (size_t)(b * SEQ + s0) * DMODEL + h * HD;
    const size_t mrow1 = mrow0 + 8 * DMODEL;
#pragma unroll
    for (int nt = 0; nt < 8; nt++) {
        const int d = nt * 8 + kq;
        __nv_bfloat16 h0, e0, h1, e1;
        split2(oa[nt][0] * il0, h0, e0);
        split2(oa[nt][1] * il0, h1, e1);
        *(uint32_t*)(outh + mrow0 + d) = pack_bf2(h0, h1);
        *(uint32_t*)(outl + mrow0 + d) = pack_bf2(e0, e1);
        split2(oa[nt][2] * il1, h0, e0);
        split2(oa[nt][3] * il1, h1, e1);
        *(uint32_t*)(outh + mrow1 + d) = pack_bf2(h0, h1);
        *(uint32_t*)(outl + mrow1 + d) = pack_bf2(e0, e1);
    }
}

// ---------------------------------------------------------------------------
extern "C" void kernel_launch(void* const* d_in, const int* in_sizes, int n_in,
                              void* d_out, int out_size)
{
    const float* x     = (const float*)d_in[0];
    const float* w_qkv = (const float*)d_in[1];
    const float* w_out = (const float*)d_in[2];
    float* out = (float*)d_out;

    float* qkv;
    cudaGetSymbolAddress((void**)&qkv, g_qkv);

    __nv_bfloat16 *xh, *xl, *wqh, *wql, *woh, *wol, *ah, *al;
    __nv_bfloat16 *qh, *ql, *kh, *kl, *vh, *vl;
    cudaGetSymbolAddress((void**)&xh,  g_xh);
    cudaGetSymbolAddress((void**)&xl,  g_xl);
    cudaGetSymbolAddress((void**)&wqh, g_wqh);
    cudaGetSymbolAddress((void**)&wql, g_wql);
    cudaGetSymbolAddress((void**)&woh, g_woh);
    cudaGetSymbolAddress((void**)&wol, g_wol);
    cudaGetSymbolAddress((void**)&ah,  g_ah);
    cudaGetSymbolAddress((void**)&al,  g_al);
    cudaGetSymbolAddress((void**)&qh,  g_qh);
    cudaGetSymbolAddress((void**)&ql,  g_ql);
    cudaGetSymbolAddress((void**)&kh,  g_kh);
    cudaGetSymbolAddress((void**)&kl,  g_kl);
    cudaGetSymbolAddress((void**)&vh,  g_vh);
    cudaGetSymbolAddress((void**)&vl,  g_vl);

    cudaFuncSetAttribute(gemm_bf16x3_kernel,
                         cudaFuncAttributeMaxDynamicSharedMemorySize, G_SMEM_BYTES);
    cudaFuncSetAttribute(attn_tc_kernel,
                         cudaFuncAttributeMaxDynamicSharedMemorySize, AT_SMEM_B);

    // 1) Convert inputs to split-bf16
    {
        int n = M_ROWS * DMODEL;
        convert_split_kernel<<<(n + 255) / 256, 256>>>(x, xh, xl, n);
    }
    transpose_split_kernel<<<dim3(QKV_N / 32, DMODEL / 32), dim3(32, 32)>>>(
        w_qkv, wqh, wql, DMODEL, QKV_N);
    transpose_split_kernel<<<dim3(DMODEL / 32, DMODEL / 32), dim3(32, 32)>>>(
        w_out, woh, wol, DMODEL, DMODEL);

    // 2) QKV projection (tensor cores)
    gemm_bf16x3_kernel<<<dim3(QKV_N / 128, M_ROWS / 128), 256, G_SMEM_BYTES>>>(
        xh, xl, wqh, wql, qkv, M_ROWS, QKV_N, DMODEL);

    // 3) RoPE + split into bf16 hi/lo
    rope_split_kernel<<<(BATCH * NH * SEQ * 32) / 256, 256>>>(
        qkv, qh, ql, kh, kl, vh, vl);

    // 4) Tensor-core causal flash attention (writes out-proj A directly)
    attn_tc_kernel<<<dim3(SEQ / 64, BATCH * NH), 128, AT_SMEM_B>>>(
        qh, ql, kh, kl, vh, vl, ah, al);

    // 5) Output projection (tensor cores)
    gemm_bf16x3_kernel<<<dim3(DMODEL / 128, M_ROWS / 128), 256, G_SMEM_BYTES>>>(
        ah, al, woh, wol, out, M_ROWS, DMODEL, DMODEL);
}

// round 9
// speedup vs baseline: 3.9884x; 1.1646x over previous
#include <cuda_runtime.h>
#include <cuda_bf16.h>
#include <math.h>
#include <stdint.h>

#define BATCH  2
#define SEQ    2048
#define DMODEL 1024
#define NH     16
#define HD     64
#define M_ROWS (BATCH * SEQ)    // 4096
#define QKV_N  (3 * DMODEL)     // 3072

// ---------------------------------------------------------------------------
// Device scratch
// ---------------------------------------------------------------------------
__device__ float g_qkv[M_ROWS * QKV_N];

__device__ __nv_bfloat16 g_xh[M_ROWS * DMODEL];
__device__ __nv_bfloat16 g_xl[M_ROWS * DMODEL];
__device__ __nv_bfloat16 g_wqh[QKV_N * DMODEL];   // [N,K] transposed
__device__ __nv_bfloat16 g_wql[QKV_N * DMODEL];
__device__ __nv_bfloat16 g_woh[DMODEL * DMODEL];  // [N,K] transposed
__device__ __nv_bfloat16 g_wol[DMODEL * DMODEL];
__device__ __nv_bfloat16 g_ah[M_ROWS * DMODEL];   // attention out hi (A of out-proj)
__device__ __nv_bfloat16 g_al[M_ROWS * DMODEL];

#define QKV_ELEMS (BATCH * NH * SEQ * HD)
__device__ __nv_bfloat16 g_qh[QKV_ELEMS];  // [B,H,S,hd], pre-scaled by 1/8
__device__ __nv_bfloat16 g_ql[QKV_ELEMS];
__device__ __nv_bfloat16 g_kh[QKV_ELEMS];
__device__ __nv_bfloat16 g_kl[QKV_ELEMS];
__device__ __nv_bfloat16 g_vh[QKV_ELEMS];
__device__ __nv_bfloat16 g_vl[QKV_ELEMS];

// ---------------------------------------------------------------------------
// Baseline-PTX helpers (no sm_103a-gated features)
// ---------------------------------------------------------------------------
__device__ __forceinline__ uint32_t smem_u32(const void* p) {
    uint32_t a;
    asm("{ .reg .u64 t; cvta.to.shared.u64 t, %1; cvt.u32.u64 %0, t; }"
        : "=r"(a) : "l"(p));
    return a;
}

#define CP_ASYNC_16(smem, gptr) \
    asm volatile("cp.async.cg.shared.global [%0], [%1], 16;\n" \
        :: "r"(smem), "l"(gptr))
#define CP_ASYNC_COMMIT() asm volatile("cp.async.commit_group;\n")
#define CP_ASYNC_WAIT(n)  asm volatile("cp.async.wait_group %0;\n" :: "n"(n))

__device__ __forceinline__ void ldsm_x4(uint32_t* r, uint32_t addr) {
    asm volatile("ldmatrix.sync.aligned.m8n8.x4.shared.b16 {%0,%1,%2,%3}, [%4];\n"
        : "=r"(r[0]), "=r"(r[1]), "=r"(r[2]), "=r"(r[3]) : "r"(addr));
}
__device__ __forceinline__ void ldsm_x4_t(uint32_t* r, uint32_t addr) {
    asm volatile("ldmatrix.sync.aligned.m8n8.x4.trans.shared.b16 {%0,%1,%2,%3}, [%4];\n"
        : "=r"(r[0]), "=r"(r[1]), "=r"(r[2]), "=r"(r[3]) : "r"(addr));
}

// D(f32) += A(bf16) * B(bf16): m16n8k16
__device__ __forceinline__ void mma16816(float* d, const uint32_t* a, const uint32_t* b) {
    asm volatile(
        "mma.sync.aligned.m16n8k16.row.col.f32.bf16.bf16.f32 "
        "{%0,%1,%2,%3}, {%4,%5,%6,%7}, {%8,%9}, {%0,%1,%2,%3};\n"
        : "+f"(d[0]), "+f"(d[1]), "+f"(d[2]), "+f"(d[3])
        : "r"(a[0]), "r"(a[1]), "r"(a[2]), "r"(a[3]), "r"(b[0]), "r"(b[1]));
}

// ---------------------------------------------------------------------------
// fp32 -> (hi, lo) bf16 split helpers
// ---------------------------------------------------------------------------
__device__ __forceinline__ void split2(float x, __nv_bfloat16& h, __nv_bfloat16& l) {
    h = __float2bfloat16(x);
    l = __float2bfloat16(x - __bfloat162float(h));
}
__device__ __forceinline__ uint32_t pack_bf2(__nv_bfloat16 a, __nv_bfloat16 b) {
    __nv_bfloat162 t; t.x = a; t.y = b;
    return *(uint32_t*)&t;
}

__global__ void convert_split_kernel(const float* __restrict__ src,
                                     __nv_bfloat16* __restrict__ hi,
                                     __nv_bfloat16* __restrict__ lo, int n) {
    int i = blockIdx.x * blockDim.x + threadIdx.x;
    if (i < n) split2(src[i], hi[i], lo[i]);
}

// W[K,N] fp32 -> WT[N,K] bf16 hi/lo (tiled transpose)
__global__ void transpose_split_kernel(const float* __restrict__ W,
                                       __nv_bfloat16* __restrict__ Thi,
                                       __nv_bfloat16* __restrict__ Tlo,
                                       int K, int N) {
    __shared__ float tile[32][33];
    int n = blockIdx.x * 32 + threadIdx.x;
    int k = blockIdx.y * 32 + threadIdx.y;
    tile[threadIdx.y][threadIdx.x] = W[(size_t)k * N + n];
    __syncthreads();
    int nt = blockIdx.x * 32 + threadIdx.y;
    int kt = blockIdx.y * 32 + threadIdx.x;
    float v = tile[threadIdx.x][threadIdx.y];
    __nv_bfloat16 h, l;
    split2(v, h, l);
    Thi[(size_t)nt * K + kt] = h;
    Tlo[(size_t)nt * K + kt] = l;
}

// ---------------------------------------------------------------------------
// Tensor-core GEMM: C = A@B, bf16 x 3-term fp32 emulation.
// Swizzled 64B-pitch smem tiles (conflict-free, no padding), 3-stage cp.async
// pipeline with one barrier per K-chunk.
// ---------------------------------------------------------------------------
#define G_BK 32
#define G_TILE_B  (128 * 64)            // 8192
#define G_STAGE_B (4 * G_TILE_B)        // 32768: Ahi,Alo,Bhi,Blo
#define G_STAGES  3
#define G_SMEM_BYTES (G_STAGES * G_STAGE_B)  // 98304

// swizzle: 16B-chunk column (0..3) xor'ed with bits [2:1] of row
__device__ __forceinline__ uint32_t gswz(int row, int chunk) {
    return (uint32_t)(row * 64 + ((chunk ^ ((row >> 1) & 3)) << 4));
}

__global__ void __launch_bounds__(256)
gemm_bf16x3_kernel(const __nv_bfloat16* __restrict__ Ahi,
                   const __nv_bfloat16* __restrict__ Alo,
                   const __nv_bfloat16* __restrict__ Bhi,
                   const __nv_bfloat16* __restrict__ Blo,
                   float* __restrict__ C, int M, int N, int K)
{
    extern __shared__ __align__(128) char dsm[];
    const uint32_t smem_base = smem_u32(dsm);

    const int tid = threadIdx.x;
    const int wid = tid >> 5;
    const int lane = tid & 31;
    const int warp_m = wid >> 1;
    const int warp_n = wid & 1;
    const int m0 = blockIdx.y * 128;
    const int n0 = blockIdx.x * 128;

    const __nv_bfloat16* gsrc[4] = {Ahi, Alo, Bhi, Blo};

    float acc[2][8][4];
#pragma unroll
    for (int i = 0; i < 2; i++)
#pragma unroll
        for (int j = 0; j < 8; j++)
#pragma unroll
            for (int c = 0; c < 4; c++) acc[i][j][c] = 0.f;

    const int nchunk = K / G_BK;

    auto issue = [&](int ci) {
        const int k0 = ci * G_BK;
        const uint32_t st = smem_base + (ci % G_STAGES) * G_STAGE_B;
#pragma unroll
        for (int i = 0; i < 8; i++) {
            const int tile = i >> 1;
            const int idx = ((i & 1) << 8) | tid;          // 0..511
            const int r = idx >> 2;                        // 0..127
            const int c = idx & 3;                         // 16B chunk
            const int grow = (tile < 2 ? m0 : n0) + r;
            const __nv_bfloat16* gp = gsrc[tile] + (size_t)grow * K + k0 + c * 8;
            CP_ASYNC_16(st + tile * G_TILE_B + gswz(r, c), gp);
        }
        CP_ASYNC_COMMIT();
    };

    issue(0);
    issue(1);

    const int a_row_off = (lane & 15);
    const int a_coff    = (lane >> 4) & 1;                 // chunk offset 0/1
    const int b_row_off = ((lane & 16) >> 1) + (lane & 7);
    const int b_coff    = (lane & 8) >> 3;                 // chunk offset 0/1

#pragma unroll 1
    for (int ci = 0; ci < nchunk; ci++) {
        CP_ASYNC_WAIT(1);
        __syncthreads();
        if (ci + 2 < nchunk) issue(ci + 2);

        const uint32_t st = smem_base + (ci % G_STAGES) * G_STAGE_B;
        const uint32_t sAhi = st;
        const uint32_t sAlo = st + G_TILE_B;
        const uint32_t sBhi = st + 2 * G_TILE_B;
        const uint32_t sBlo = st + 3 * G_TILE_B;

#pragma unroll
        for (int ks = 0; ks < 2; ks++) {
            uint32_t ahi[2][4], alo[2][4];
#pragma unroll
            for (int mt = 0; mt < 2; mt++) {
                const int ar = warp_m * 32 + mt * 16 + a_row_off;
                const uint32_t aoff = gswz(ar, ks * 2 + a_coff);
                ldsm_x4(ahi[mt], sAhi + aoff);
                ldsm_x4(alo[mt], sAlo + aoff);
            }
#pragma unroll
            for (int ntp = 0; ntp < 4; ntp++) {
                const int br = warp_n * 64 + ntp * 16 + b_row_off;
                const uint32_t boff = gswz(br, ks * 2 + b_coff);
                uint32_t bh4[4], bl4[4];
                ldsm_x4(bh4, sBhi + boff);
                ldsm_x4(bl4, sBlo + boff);
#pragma unroll
                for (int mt = 0; mt < 2; mt++)
#pragma unroll
                    for (int j = 0; j < 2; j++) {
                        float* d = acc[mt][2 * ntp + j];
                        mma16816(d, ahi[mt], &bh4[2 * j]);
                        mma16816(d, ahi[mt], &bl4[2 * j]);
                        mma16816(d, alo[mt], &bh4[2 * j]);
                    }
            }
        }
    }

    const int quad = lane >> 2;
    const int tq = lane & 3;
    float* Cw = C + (size_t)(m0 + warp_m * 32) * N + n0 + warp_n * 64;
#pragma unroll
    for (int mt = 0; mt < 2; mt++)
#pragma unroll
        for (int nt = 0; nt < 8; nt++) {
            const int r = mt * 16 + quad;
            const int c = nt * 8 + tq * 2;
            *(float2*)(Cw + (size_t)r * N + c) =
                make_float2(acc[mt][nt][0], acc[mt][nt][1]);
            *(float2*)(Cw + (size_t)(r + 8) * N + c) =
                make_float2(acc[mt][nt][2], acc[mt][nt][3]);
        }
}

// ---------------------------------------------------------------------------
// RoPE + split into bf16 hi/lo. q pre-scaled by 1/8 (softmax scale).
// ---------------------------------------------------------------------------
__global__ void rope_split_kernel(const float* __restrict__ qkv,
                                  __nv_bfloat16* __restrict__ qh, __nv_bfloat16* __restrict__ ql,
                                  __nv_bfloat16* __restrict__ kh, __nv_bfloat16* __restrict__ kl,
                                  __nv_bfloat16* __restrict__ vh, __nv_bfloat16* __restrict__ vl)
{
    int idx = blockIdx.x * blockDim.x + threadIdx.x;   // < 2^21
    int j = idx & 31;
    int s = (idx >> 5) & 2047;
    int h = (idx >> 16) & 15;
    int b = idx >> 20;

    float inv_freq = powf(10000.0f, -(float)j * (1.0f / 32.0f));
    float ang = (float)s * inv_freq;
    float sn, cs;
    sincosf(ang, &sn, &cs);

    const float* src = qkv + ((size_t)(b * SEQ + s)) * QKV_N + h * HD;
    float q0 = src[j],          q1 = src[j + 32];
    float k0 = src[DMODEL + j], k1 = src[DMODEL + j + 32];
    float v0 = src[2 * DMODEL + j], v1 = src[2 * DMODEL + j + 32];

    float qa = (q0 * cs - q1 * sn) * 0.125f;
    float qb = (q1 * cs + q0 * sn) * 0.125f;
    float ka = k0 * cs - k1 * sn;
    float kb = k1 * cs + k0 * sn;

    size_t dst = ((size_t)((b * NH + h) * SEQ) + s) * HD;
    __nv_bfloat16 hh, ll;
    split2(qa, hh, ll); qh[dst + j] = hh;      ql[dst + j] = ll;
    split2(qb, hh, ll); qh[dst + j + 32] = hh; ql[dst + j + 32] = ll;
    split2(ka, hh, ll); kh[dst + j] = hh;      kl[dst + j] = ll;
    split2(kb, hh, ll); kh[dst + j + 32] = hh; kl[dst + j + 32] = ll;
    split2(v0, hh, ll); vh[dst + j] = hh;      vl[dst + j] = ll;
    split2(v1, hh, ll); vh[dst + j + 32] = hh; vl[dst + j + 32] = ll;
}

// ---------------------------------------------------------------------------
// Tensor-core causal flash attention (bf16 x 3-term emulation).
// Swizzled 128B-pitch K/V tiles (no pad -> 64KB smem, 3 CTAs/SM),
// double-buffered cp.async, one barrier per key tile.
// ---------------------------------------------------------------------------
#define AT_TILE_B  (64 * 128)             // 8192
#define AT_STAGE_B (4 * AT_TILE_B)        // 32768
#define AT_SMEM_B  (2 * AT_STAGE_B)       // 65536

// swizzle for 128B rows: chunk (0..7) xor bits [2:0] of row
__device__ __forceinline__ uint32_t aswz(int row, int chunk) {
    return (uint32_t)(row * 128 + ((chunk ^ (row & 7)) << 4));
}

__global__ void __launch_bounds__(128)
attn_tc_kernel(const __nv_bfloat16* __restrict__ qh, const __nv_bfloat16* __restrict__ ql,
               const __nv_bfloat16* __restrict__ kh, const __nv_bfloat16* __restrict__ kl,
               const __nv_bfloat16* __restrict__ vh, const __nv_bfloat16* __restrict__ vl,
               __nv_bfloat16* __restrict__ outh, __nv_bfloat16* __restrict__ outl)
{
    extern __shared__ __align__(128) char dsm[];
    const uint32_t sb = smem_u32(dsm);

    const int bh = blockIdx.y;
    const int qt = gridDim.x - 1 - blockIdx.x;   // heavy tiles first
    const int tid = threadIdx.x;
    const int wid = tid >> 5;
    const int lane = tid & 31;
    const int kq = (lane & 3) * 2;               // fragment col offset
    const size_t base = (size_t)bh * SEQ * HD;

    const __nv_bfloat16* khp = kh + base;
    const __nv_bfloat16* klp = kl + base;
    const __nv_bfloat16* vhp = vh + base;
    const __nv_bfloat16* vlp = vl + base;

    // ---- Q fragments (register resident) ----
    const int rloc = wid * 16 + (lane >> 2);     // local q row (0..63), +8 pair
    const int grow = qt * 64 + rloc;
    uint32_t qfh[4][4], qfl[4][4];
#pragma unroll
    for (int kc = 0; kc < 4; kc++) {
        size_t o = base + (size_t)grow * HD + kc * 16 + kq;
        qfh[kc][0] = *(const uint32_t*)(qh + o);
        qfh[kc][1] = *(const uint32_t*)(qh + o + 8 * HD);
        qfh[kc][2] = *(const uint32_t*)(qh + o + 8);
        qfh[kc][3] = *(const uint32_t*)(qh + o + 8 * HD + 8);
        qfl[kc][0] = *(const uint32_t*)(ql + o);
        qfl[kc][1] = *(const uint32_t*)(ql + o + 8 * HD);
        qfl[kc][2] = *(const uint32_t*)(ql + o + 8);
        qfl[kc][3] = *(const uint32_t*)(ql + o + 8 * HD + 8);
    }

    float oa[8][4];
#pragma unroll
    for (int i = 0; i < 8; i++)
#pragma unroll
        for (int c = 0; c < 4; c++) oa[i][c] = 0.f;
    float m0 = -INFINITY, m1 = -INFINITY, l0 = 0.f, l1 = 0.f;

    auto issue = [&](int kt) {
        const uint32_t st = sb + (kt & 1) * AT_STAGE_B;
        const __nv_bfloat16* srcs[4] = {khp, klp, vhp, vlp};
        const int kr0 = kt * 64;
#pragma unroll
        for (int t = 0; t < 4; t++) {
#pragma unroll
            for (int i = 0; i < 4; i++) {
                int c = i * 128 + tid;           // 0..511
                int row = c >> 3, col = c & 7;
                CP_ASYNC_16(st + t * AT_TILE_B + aswz(row, col),
                            srcs[t] + (size_t)(kr0 + row) * HD + col * 8);
            }
        }
        CP_ASYNC_COMMIT();
    };

    issue(0);

    const int b_row = ((lane & 16) >> 1) + (lane & 7);
    const int b_coff = (lane & 8) >> 3;
    const int vg    = lane >> 3;                 // 0..3 for trans-ldmatrix groups

#pragma unroll 1
    for (int kt = 0; kt <= qt; kt++) {
        CP_ASYNC_WAIT(0);
        __syncthreads();
        if (kt < qt) issue(kt + 1);

        const uint32_t st  = sb + (kt & 1) * AT_STAGE_B;
        const uint32_t sKh = st;
        const uint32_t sKl = st + AT_TILE_B;
        const uint32_t sVh = st + 2 * AT_TILE_B;
        const uint32_t sVl = st + 3 * AT_TILE_B;

        // ---- S = Q @ K^T (3-term) ----
        float sacc[8][4];
#pragma unroll
        for (int i = 0; i < 8; i++)
#pragma unroll
            for (int c = 0; c < 4; c++) sacc[i][c] = 0.f;

#pragma unroll
        for (int kc = 0; kc < 4; kc++) {
#pragma unroll
            for (int np = 0; np < 4; np++) {
                const int krow = np * 16 + b_row;
                const uint32_t addr = aswz(krow, kc * 2 + b_coff);
                uint32_t bh4[4], bl4[4];
                ldsm_x4(bh4, sKh + addr);
                ldsm_x4(bl4, sKl + addr);
#pragma unroll
                for (int j = 0; j < 2; j++) {
                    float* d = sacc[2 * np + j];
                    mma16816(d, qfh[kc], &bh4[2 * j]);
                    mma16816(d, qfh[kc], &bl4[2 * j]);
                    mma16816(d, qfl[kc], &bh4[2 * j]);
                }
            }
        }

        // ---- causal mask on the diagonal tile ----
        if (kt == qt) {
#pragma unroll
            for (int nt = 0; nt < 8; nt++) {
                int col = nt * 8 + kq;
                if (col > rloc)      sacc[nt][0] = -INFINITY;
                if (col + 1 > rloc)  sacc[nt][1] = -INFINITY;
                if (col > rloc + 8)      sacc[nt][2] = -INFINITY;
                if (col + 1 > rloc + 8)  sacc[nt][3] = -INFINITY;
            }
        }

        // ---- online softmax (fragment layout) ----
        float rm0 = -INFINITY, rm1 = -INFINITY;
#pragma unroll
        for (int nt = 0; nt < 8; nt++) {
            rm0 = fmaxf(rm0, fmaxf(sacc[nt][0], sacc[nt][1]));
            rm1 = fmaxf(rm1, fmaxf(sacc[nt][2], sacc[nt][3]));
        }
        rm0 = fmaxf(rm0, __shfl_xor_sync(0xffffffffu, rm0, 1));
        rm0 = fmaxf(rm0, __shfl_xor_sync(0xffffffffu, rm0, 2));
        rm1 = fmaxf(rm1, __shfl_xor_sync(0xffffffffu, rm1, 1));
        rm1 = fmaxf(rm1, __shfl_xor_sync(0xffffffffu, rm1, 2));

        float mn0 = fmaxf(m0, rm0), mn1 = fmaxf(m1, rm1);
        float c0 = __expf(m0 - mn0), c1 = __expf(m1 - mn1);
        m0 = mn0; m1 = mn1;
        l0 *= c0; l1 *= c1;
#pragma unroll
        for (int nt = 0; nt < 8; nt++) {
            oa[nt][0] *= c0; oa[nt][1] *= c0;
            oa[nt][2] *= c1; oa[nt][3] *= c1;
        }

        // ---- P = exp(S - m), split + repack into A fragments ----
        uint32_t pfh[4][4], pfl[4][4];
        float ps0 = 0.f, ps1 = 0.f;
#pragma unroll
        for (int np = 0; np < 4; np++) {
#pragma unroll
            for (int j = 0; j < 2; j++) {
                const int t = 2 * np + j;
                float p0 = __expf(sacc[t][0] - m0);
                float p1 = __expf(sacc[t][1] - m0);
                float p2 = __expf(sacc[t][2] - m1);
                float p3 = __expf(sacc[t][3] - m1);
                ps0 += p0 + p1; ps1 += p2 + p3;
                __nv_bfloat16 h0, e0, h1, e1, h2, e2, h3, e3;
                split2(p0, h0, e0); split2(p1, h1, e1);
                split2(p2, h2, e2); split2(p3, h3, e3);
                pfh[np][2 * j]     = pack_bf2(h0, h1);
                pfh[np][2 * j + 1] = pack_bf2(h2, h3);
                pfl[np][2 * j]     = pack_bf2(e0, e1);
                pfl[np][2 * j + 1] = pack_bf2(e2, e3);
            }
        }
        ps0 += __shfl_xor_sync(0xffffffffu, ps0, 1);
        ps0 += __shfl_xor_sync(0xffffffffu, ps0, 2);
        ps1 += __shfl_xor_sync(0xffffffffu, ps1, 1);
        ps1 += __shfl_xor_sync(0xffffffffu, ps1, 2);
        l0 += ps0; l1 += ps1;

        // ---- O += P @ V (3-term), V^T fragments via ldmatrix.trans ----
#pragma unroll
        for (int kc2 = 0; kc2 < 4; kc2++) {
#pragma unroll
            for (int dp = 0; dp < 4; dp++) {
                const int vrow = kc2 * 16 + (lane & 7) + ((vg & 1) << 3);
                const uint32_t addr = aswz(vrow, dp * 2 + (vg >> 1));
                uint32_t bvh[4], bvl[4];
                ldsm_x4_t(bvh, sVh + addr);
                ldsm_x4_t(bvl, sVl + addr);
#pragma unroll
                for (int j = 0; j < 2; j++) {
                    float* d = oa[2 * dp + j];
                    mma16816(d, pfh[kc2], &bvh[2 * j]);
                    mma16816(d, pfl[kc2], &bvh[2 * j]);
                    mma16816(d, pfh[kc2], &bvl[2 * j]);
                }
            }
        }
    }

    // ---- epilogue: normalize, split, write [B*S, H*hd] bf16 hi/lo ----
    const float il0 = 1.0f / l0, il1 = 1.0f / l1;
    const int b = bh >> 4, h = bh & 15;
    const int s0 = qt * 64 + wid * 16 + (lane >> 2);
    const size_t mrow0 = (size_t)(b * SEQ + s0) * DMODEL + h * HD;
    const size_t mrow1 = mrow0 + 8 * DMODEL;
#pragma unroll
    for (int nt = 0; nt < 8; nt++) {
        const int d = nt * 8 + kq;
        __nv_bfloat16 h0, e0, h1, e1;
        split2(oa[nt][0] * il0, h0, e0);
        split2(oa[nt][1] * il0, h1, e1);
        *(uint32_t*)(outh + mrow0 + d) = pack_bf2(h0, h1);
        *(uint32_t*)(outl + mrow0 + d) = pack_bf2(e0, e1);
        split2(oa[nt][2] * il1, h0, e0);
        split2(oa[nt][3] * il1, h1, e1);
        *(uint32_t*)(outh + mrow1 + d) = pack_bf2(h0, h1);
        *(uint32_t*)(outl + mrow1 + d) = pack_bf2(e0, e1);
    }
}

// ---------------------------------------------------------------------------
extern "C" void kernel_launch(void* const* d_in, const int* in_sizes, int n_in,
                              void* d_out, int out_size)
{
    const float* x     = (const float*)d_in[0];
    const float* w_qkv = (const float*)d_in[1];
    const float* w_out = (const float*)d_in[2];
    float* out = (float*)d_out;

    float* qkv;
    cudaGetSymbolAddress((void**)&qkv, g_qkv);

    __nv_bfloat16 *xh, *xl, *wqh, *wql, *woh, *wol, *ah, *al;
    __nv_bfloat16 *qh, *ql, *kh, *kl, *vh, *vl;
    cudaGetSymbolAddress((void**)&xh,  g_xh);
    cudaGetSymbolAddress((void**)&xl,  g_xl);
    cudaGetSymbolAddress((void**)&wqh, g_wqh);
    cudaGetSymbolAddress((void**)&wql, g_wql);
    cudaGetSymbolAddress((void**)&woh, g_woh);
    cudaGetSymbolAddress((void**)&wol, g_wol);
    cudaGetSymbolAddress((void**)&ah,  g_ah);
    cudaGetSymbolAddress((void**)&al,  g_al);
    cudaGetSymbolAddress((void**)&qh,  g_qh);
    cudaGetSymbolAddress((void**)&ql,  g_ql);
    cudaGetSymbolAddress((void**)&kh,  g_kh);
    cudaGetSymbolAddress((void**)&kl,  g_kl);
    cudaGetSymbolAddress((void**)&vh,  g_vh);
    cudaGetSymbolAddress((void**)&vl,  g_vl);

    cudaFuncSetAttribute(gemm_bf16x3_kernel,
                         cudaFuncAttributeMaxDynamicSharedMemorySize, G_SMEM_BYTES);
    cudaFuncSetAttribute(attn_tc_kernel,
                         cudaFuncAttributeMaxDynamicSharedMemorySize, AT_SMEM_B);

    // 1) Convert inputs to split-bf16
    {
        int n = M_ROWS * DMODEL;
        convert_split_kernel<<<(n + 255) / 256, 256>>>(x, xh, xl, n);
    }
    transpose_split_kernel<<<dim3(QKV_N / 32, DMODEL / 32), dim3(32, 32)>>>(
        w_qkv, wqh, wql, DMODEL, QKV_N);
    transpose_split_kernel<<<dim3(DMODEL / 32, DMODEL / 32), dim3(32, 32)>>>(
        w_out, woh, wol, DMODEL, DMODEL);

    // 2) QKV projection (tensor cores)
    gemm_bf16x3_kernel<<<dim3(QKV_N / 128, M_ROWS / 128), 256, G_SMEM_BYTES>>>(
        xh, xl, wqh, wql, qkv, M_ROWS, QKV_N, DMODEL);

    // 3) RoPE + split into bf16 hi/lo
    rope_split_kernel<<<(BATCH * NH * SEQ * 32) / 256, 256>>>(
        qkv, qh, ql, kh, kl, vh, vl);

    // 4) Tensor-core causal flash attention (writes out-proj A directly)
    attn_tc_kernel<<<dim3(SEQ / 64, BATCH * NH), 128, AT_SMEM_B>>>(
        qh, ql, kh, kl, vh, vl, ah, al);

    // 5) Output projection (tensor cores)
    gemm_bf16x3_kernel<<<dim3(DMODEL / 128, M_ROWS / 128), 256, G_SMEM_BYTES>>>(
        ah, al, woh, wol, out, M_ROWS, DMODEL, DMODEL);
}

// round 10
// speedup vs baseline: 4.0545x; 1.0166x over previous
#include <cuda_runtime.h>
#include <cuda_bf16.h>
#include <math.h>
#include <stdint.h>

#define BATCH  2
#define SEQ    2048
#define DMODEL 1024
#define NH     16
#define HD     64
#define M_ROWS (BATCH * SEQ)    // 4096
#define QKV_N  (3 * DMODEL)     // 3072

// ---------------------------------------------------------------------------
// Device scratch
// ---------------------------------------------------------------------------
__device__ __nv_bfloat16 g_xh[M_ROWS * DMODEL];
__device__ __nv_bfloat16 g_xl[M_ROWS * DMODEL];
__device__ __nv_bfloat16 g_wqh[QKV_N * DMODEL];   // [N,K] transposed
__device__ __nv_bfloat16 g_wql[QKV_N * DMODEL];
__device__ __nv_bfloat16 g_woh[DMODEL * DMODEL];  // [N,K] transposed
__device__ __nv_bfloat16 g_wol[DMODEL * DMODEL];
__device__ __nv_bfloat16 g_ah[M_ROWS * DMODEL];   // attention out hi (A of out-proj)
__device__ __nv_bfloat16 g_al[M_ROWS * DMODEL];

#define QKV_ELEMS (BATCH * NH * SEQ * HD)
__device__ __nv_bfloat16 g_qh[QKV_ELEMS];  // [B,H,S,hd], pre-scaled by 1/8
__device__ __nv_bfloat16 g_ql[QKV_ELEMS];
__device__ __nv_bfloat16 g_kh[QKV_ELEMS];
__device__ __nv_bfloat16 g_kl[QKV_ELEMS];
__device__ __nv_bfloat16 g_vh[QKV_ELEMS];
__device__ __nv_bfloat16 g_vl[QKV_ELEMS];

__device__ float2 g_rope_tab[SEQ * 32];    // (cos, sin) per (s, j)

// ---------------------------------------------------------------------------
// Baseline-PTX helpers (no sm_103a-gated features)
// ---------------------------------------------------------------------------
__device__ __forceinline__ uint32_t smem_u32(const void* p) {
    uint32_t a;
    asm("{ .reg .u64 t; cvta.to.shared.u64 t, %1; cvt.u32.u64 %0, t; }"
        : "=r"(a) : "l"(p));
    return a;
}

#define CP_ASYNC_16(smem, gptr) \
    asm volatile("cp.async.cg.shared.global [%0], [%1], 16;\n" \
        :: "r"(smem), "l"(gptr))
#define CP_ASYNC_COMMIT() asm volatile("cp.async.commit_group;\n")
#define CP_ASYNC_WAIT(n)  asm volatile("cp.async.wait_group %0;\n" :: "n"(n))

__device__ __forceinline__ void ldsm_x4(uint32_t* r, uint32_t addr) {
    asm volatile("ldmatrix.sync.aligned.m8n8.x4.shared.b16 {%0,%1,%2,%3}, [%4];\n"
        : "=r"(r[0]), "=r"(r[1]), "=r"(r[2]), "=r"(r[3]) : "r"(addr));
}
__device__ __forceinline__ void ldsm_x4_t(uint32_t* r, uint32_t addr) {
    asm volatile("ldmatrix.sync.aligned.m8n8.x4.trans.shared.b16 {%0,%1,%2,%3}, [%4];\n"
        : "=r"(r[0]), "=r"(r[1]), "=r"(r[2]), "=r"(r[3]) : "r"(addr));
}

// D(f32) += A(bf16) * B(bf16): m16n8k16
__device__ __forceinline__ void mma16816(float* d, const uint32_t* a, const uint32_t* b) {
    asm volatile(
        "mma.sync.aligned.m16n8k16.row.col.f32.bf16.bf16.f32 "
        "{%0,%1,%2,%3}, {%4,%5,%6,%7}, {%8,%9}, {%0,%1,%2,%3};\n"
        : "+f"(d[0]), "+f"(d[1]), "+f"(d[2]), "+f"(d[3])
        : "r"(a[0]), "r"(a[1]), "r"(a[2]), "r"(a[3]), "r"(b[0]), "r"(b[1]));
}

// ---------------------------------------------------------------------------
// fp32 -> (hi, lo) bf16 split helpers
// ---------------------------------------------------------------------------
__device__ __forceinline__ void split2(float x, __nv_bfloat16& h, __nv_bfloat16& l) {
    h = __float2bfloat16(x);
    l = __float2bfloat16(x - __bfloat162float(h));
}
__device__ __forceinline__ uint32_t pack_bf2(__nv_bfloat16 a, __nv_bfloat16 b) {
    __nv_bfloat162 t; t.x = a; t.y = b;
    return *(uint32_t*)&t;
}

__global__ void rope_table_kernel(float2* tab) {
    int i = blockIdx.x * blockDim.x + threadIdx.x;   // < SEQ*32
    int j = i & 31, s = i >> 5;
    float inv_freq = powf(10000.0f, -(float)j * (1.0f / 32.0f));
    float sn, cs;
    sincosf((float)s * inv_freq, &sn, &cs);
    tab[i] = make_float2(cs, sn);
}

__global__ void convert_split_kernel(const float* __restrict__ src,
                                     __nv_bfloat16* __restrict__ hi,
                                     __nv_bfloat16* __restrict__ lo, int n) {
    int i = blockIdx.x * blockDim.x + threadIdx.x;
    if (i < n) split2(src[i], hi[i], lo[i]);
}

// W[K,N] fp32 -> WT[N,K] bf16 hi/lo (tiled transpose)
__global__ void transpose_split_kernel(const float* __restrict__ W,
                                       __nv_bfloat16* __restrict__ Thi,
                                       __nv_bfloat16* __restrict__ Tlo,
                                       int K, int N) {
    __shared__ float tile[32][33];
    int n = blockIdx.x * 32 + threadIdx.x;
    int k = blockIdx.y * 32 + threadIdx.y;
    tile[threadIdx.y][threadIdx.x] = W[(size_t)k * N + n];
    __syncthreads();
    int nt = blockIdx.x * 32 + threadIdx.y;
    int kt = blockIdx.y * 32 + threadIdx.x;
    float v = tile[threadIdx.x][threadIdx.y];
    __nv_bfloat16 h, l;
    split2(v, h, l);
    Thi[(size_t)nt * K + kt] = h;
    Tlo[(size_t)nt * K + kt] = l;
}

// ---------------------------------------------------------------------------
// Tensor-core GEMM: C = A@B, bf16 x 3-term fp32 emulation.
// mode 0: store fp32 C.
// mode 1: QKV fused epilogue — apply RoPE (q,k) + 1/8 q-scale, split to bf16
//         hi/lo, write q/k/v in [B,H,S,hd]. Warp n-tile (64 cols) == one head;
//         RoPE partner cols live in the same thread at fragment index nt^4.
// ---------------------------------------------------------------------------
#define G_BK 32
#define G_TILE_B  (128 * 64)            // 8192
#define G_STAGE_B (4 * G_TILE_B)        // 32768: Ahi,Alo,Bhi,Blo
#define G_STAGES  3
#define G_SMEM_BYTES (G_STAGES * G_STAGE_B)  // 98304

__device__ __forceinline__ uint32_t gswz(int row, int chunk) {
    return (uint32_t)(row * 64 + ((chunk ^ ((row >> 1) & 3)) << 4));
}

__global__ void __launch_bounds__(256)
gemm_bf16x3_kernel(const __nv_bfloat16* __restrict__ Ahi,
                   const __nv_bfloat16* __restrict__ Alo,
                   const __nv_bfloat16* __restrict__ Bhi,
                   const __nv_bfloat16* __restrict__ Blo,
                   float* __restrict__ C,
                   __nv_bfloat16* __restrict__ qh, __nv_bfloat16* __restrict__ ql,
                   __nv_bfloat16* __restrict__ kh, __nv_bfloat16* __restrict__ kl,
                   __nv_bfloat16* __restrict__ vh, __nv_bfloat16* __restrict__ vl,
                   int M, int N, int K, int mode)
{
    extern __shared__ __align__(128) char dsm[];
    const uint32_t smem_base = smem_u32(dsm);

    const int tid = threadIdx.x;
    const int wid = tid >> 5;
    const int lane = tid & 31;
    const int warp_m = wid >> 1;
    const int warp_n = wid & 1;
    const int m0 = blockIdx.y * 128;
    const int n0 = blockIdx.x * 128;

    const __nv_bfloat16* gsrc[4] = {Ahi, Alo, Bhi, Blo};

    float acc[2][8][4];
#pragma unroll
    for (int i = 0; i < 2; i++)
#pragma unroll
        for (int j = 0; j < 8; j++)
#pragma unroll
            for (int c = 0; c < 4; c++) acc[i][j][c] = 0.f;

    const int nchunk = K / G_BK;

    auto issue = [&](int ci) {
        const int k0 = ci * G_BK;
        const uint32_t st = smem_base + (ci % G_STAGES) * G_STAGE_B;
#pragma unroll
        for (int i = 0; i < 8; i++) {
            const int tile = i >> 1;
            const int idx = ((i & 1) << 8) | tid;          // 0..511
            const int r = idx >> 2;                        // 0..127
            const int c = idx & 3;                         // 16B chunk
            const int grow = (tile < 2 ? m0 : n0) + r;
            const __nv_bfloat16* gp = gsrc[tile] + (size_t)grow * K + k0 + c * 8;
            CP_ASYNC_16(st + tile * G_TILE_B + gswz(r, c), gp);
        }
        CP_ASYNC_COMMIT();
    };

    issue(0);
    issue(1);

    const int a_row_off = (lane & 15);
    const int a_coff    = (lane >> 4) & 1;
    const int b_row_off = ((lane & 16) >> 1) + (lane & 7);
    const int b_coff    = (lane & 8) >> 3;

#pragma unroll 1
    for (int ci = 0; ci < nchunk; ci++) {
        CP_ASYNC_WAIT(1);
        __syncthreads();
        if (ci + 2 < nchunk) issue(ci + 2);

        const uint32_t st = smem_base + (ci % G_STAGES) * G_STAGE_B;
        const uint32_t sAhi = st;
        const uint32_t sAlo = st + G_TILE_B;
        const uint32_t sBhi = st + 2 * G_TILE_B;
        const uint32_t sBlo = st + 3 * G_TILE_B;

#pragma unroll
        for (int ks = 0; ks < 2; ks++) {
            uint32_t ahi[2][4], alo[2][4];
#pragma unroll
            for (int mt = 0; mt < 2; mt++) {
                const int ar = warp_m * 32 + mt * 16 + a_row_off;
                const uint32_t aoff = gswz(ar, ks * 2 + a_coff);
                ldsm_x4(ahi[mt], sAhi + aoff);
                ldsm_x4(alo[mt], sAlo + aoff);
            }
#pragma unroll
            for (int ntp = 0; ntp < 4; ntp++) {
                const int br = warp_n * 64 + ntp * 16 + b_row_off;
                const uint32_t boff = gswz(br, ks * 2 + b_coff);
                uint32_t bh4[4], bl4[4];
                ldsm_x4(bh4, sBhi + boff);
                ldsm_x4(bl4, sBlo + boff);
#pragma unroll
                for (int mt = 0; mt < 2; mt++)
#pragma unroll
                    for (int j = 0; j < 2; j++) {
                        float* d = acc[mt][2 * ntp + j];
                        mma16816(d, ahi[mt], &bh4[2 * j]);
                        mma16816(d, ahi[mt], &bl4[2 * j]);
                        mma16816(d, alo[mt], &bh4[2 * j]);
                    }
            }
        }
    }

    const int quad = lane >> 2;
    const int tq = lane & 3;

    if (mode == 0) {
        float* Cw = C + (size_t)(m0 + warp_m * 32) * N + n0 + warp_n * 64;
#pragma unroll
        for (int mt = 0; mt < 2; mt++)
#pragma unroll
            for (int nt = 0; nt < 8; nt++) {
                const int r = mt * 16 + quad;
                const int c = nt * 8 + tq * 2;
                *(float2*)(Cw + (size_t)r * N + c) =
                    make_float2(acc[mt][nt][0], acc[mt][nt][1]);
                *(float2*)(Cw + (size_t)(r + 8) * N + c) =
                    make_float2(acc[mt][nt][2], acc[mt][nt][3]);
            }
        return;
    }

    // ---- mode 1: fused RoPE + split epilogue for QKV ----
    const int ng0 = n0 + warp_n * 64;          // 64-aligned -> single head
    const int sec = ng0 >> 10;                 // 0=q, 1=k, 2=v
    const int hh  = (ng0 & 1023) >> 6;
    __nv_bfloat16* ph = (sec == 0) ? qh : (sec == 1) ? kh : vh;
    __nv_bfloat16* pl = (sec == 0) ? ql : (sec == 1) ? kl : vl;

#pragma unroll
    for (int mt = 0; mt < 2; mt++) {
#pragma unroll
        for (int half = 0; half < 2; half++) {
            const int r_g = m0 + warp_m * 32 + mt * 16 + quad + half * 8;
            const int b = r_g >> 11, s = r_g & 2047;
            const size_t dst = ((size_t)((b * NH + hh) * SEQ) + s) * HD;
            const float2* trow = g_rope_tab + s * 32;
#pragma unroll
            for (int nt = 0; nt < 8; nt++) {
                const int d0 = nt * 8 + tq * 2;
                float v0 = acc[mt][nt][half * 2 + 0];
                float v1 = acc[mt][nt][half * 2 + 1];
                float r0, r1;
                if (sec < 2) {
                    const float p0 = acc[mt][nt ^ 4][half * 2 + 0];
                    const float p1 = acc[mt][nt ^ 4][half * 2 + 1];
                    const int j0 = d0 & 31;
                    const float2 t0 = trow[j0];
                    const float2 t1 = trow[j0 + 1];
                    if (nt < 4) { r0 = v0 * t0.x - p0 * t0.y; r1 = v1 * t1.x - p1 * t1.y; }
                    else        { r0 = v0 * t0.x + p0 * t0.y; r1 = v1 * t1.x + p1 * t1.y; }
                    if (sec == 0) { r0 *= 0.125f; r1 *= 0.125f; }
                } else { r0 = v0; r1 = v1; }
                __nv_bfloat16 h0, e0, h1, e1;
                split2(r0, h0, e0);
                split2(r1, h1, e1);
                *(uint32_t*)(ph + dst + d0) = pack_bf2(h0, h1);
                *(uint32_t*)(pl + dst + d0) = pack_bf2(e0, e1);
            }
        }
    }
}

// ---------------------------------------------------------------------------
// Tensor-core causal flash attention (bf16 x 3-term emulation).
// 256 threads = 8 warps, q-tile 128 (16 rows/warp). Key tiles of 64.
// Warps fully below a masked key tile skip its compute entirely.
// ---------------------------------------------------------------------------
#define AT_TILE_B  (64 * 128)             // 8192
#define AT_STAGE_B (4 * AT_TILE_B)        // 32768
#define AT_SMEM_B  (2 * AT_STAGE_B)       // 65536

__device__ __forceinline__ uint32_t aswz(int row, int chunk) {
    return (uint32_t)(row * 128 + ((chunk ^ (row & 7)) << 4));
}

__global__ void __launch_bounds__(256)
attn_tc_kernel(const __nv_bfloat16* __restrict__ qh, const __nv_bfloat16* __restrict__ ql,
               const __nv_bfloat16* __restrict__ kh, const __nv_bfloat16* __restrict__ kl,
               const __nv_bfloat16* __restrict__ vh, const __nv_bfloat16* __restrict__ vl,
               __nv_bfloat16* __restrict__ outh, __nv_bfloat16* __restrict__ outl)
{
    extern __shared__ __align__(128) char dsm[];
    const uint32_t sb = smem_u32(dsm);

    const int bh = blockIdx.y;
    const int qt = gridDim.x - 1 - blockIdx.x;   // heavy q-tiles first
    const int tid = threadIdx.x;
    const int wid = tid >> 5;
    const int lane = tid & 31;
    const int kq = (lane & 3) * 2;               // fragment col offset
    const size_t base = (size_t)bh * SEQ * HD;

    const __nv_bfloat16* khp = kh + base;
    const __nv_bfloat16* klp = kl + base;
    const __nv_bfloat16* vhp = vh + base;
    const __nv_bfloat16* vlp = vl + base;

    // ---- Q fragments (register resident) ----
    const int rloc = wid * 16 + (lane >> 2);     // local q row (0..127), +8 pair
    const int grow = qt * 128 + rloc;            // global q row
    uint32_t qfh[4][4], qfl[4][4];
#pragma unroll
    for (int kc = 0; kc < 4; kc++) {
        size_t o = base + (size_t)grow * HD + kc * 16 + kq;
        qfh[kc][0] = *(const uint32_t*)(qh + o);
        qfh[kc][1] = *(const uint32_t*)(qh + o + 8 * HD);
        qfh[kc][2] = *(const uint32_t*)(qh + o + 8);
        qfh[kc][3] = *(const uint32_t*)(qh + o + 8 * HD + 8);
        qfl[kc][0] = *(const uint32_t*)(ql + o);
        qfl[kc][1] = *(const uint32_t*)(ql + o + 8 * HD);
        qfl[kc][2] = *(const uint32_t*)(ql + o + 8);
        qfl[kc][3] = *(const uint32_t*)(ql + o + 8 * HD + 8);
    }

    float oa[8][4];
#pragma unroll
    for (int i = 0; i < 8; i++)
#pragma unroll
        for (int c = 0; c < 4; c++) oa[i][c] = 0.f;
    float m0 = -INFINITY, m1 = -INFINITY, l0 = 0.f, l1 = 0.f;

    auto issue = [&](int kt) {
        const uint32_t st = sb + (kt & 1) * AT_STAGE_B;
        const __nv_bfloat16* srcs[4] = {khp, klp, vhp, vlp};
        const int kr0 = kt * 64;
#pragma unroll
        for (int t = 0; t < 4; t++) {
#pragma unroll
            for (int i = 0; i < 2; i++) {
                int c = i * 256 + tid;           // 0..511
                int row = c >> 3, col = c & 7;
                CP_ASYNC_16(st + t * AT_TILE_B + aswz(row, col),
                            srcs[t] + (size_t)(kr0 + row) * HD + col * 8);
            }
        }
        CP_ASYNC_COMMIT();
    };

    issue(0);

    const int b_row = ((lane & 16) >> 1) + (lane & 7);
    const int b_coff = (lane & 8) >> 3;
    const int vg    = lane >> 3;

    const int nkt = 2 * qt + 2;                  // key tiles: 0 .. 2qt+1

#pragma unroll 1
    for (int kt = 0; kt < nkt; kt++) {
        CP_ASYNC_WAIT(0);
        __syncthreads();
        if (kt + 1 < nkt) issue(kt + 1);

        const int tile_k0 = kt * 64;
        const int wrow_min = qt * 128 + wid * 16;
        const bool full_skip = tile_k0 > wrow_min + 15;
        const bool need_mask = !full_skip && (tile_k0 + 63 > wrow_min);

        if (!full_skip) {
            const uint32_t st  = sb + (kt & 1) * AT_STAGE_B;
            const uint32_t sKh = st;
            const uint32_t sKl = st + AT_TILE_B;
            const uint32_t sVh = st + 2 * AT_TILE_B;
            const uint32_t sVl = st + 3 * AT_TILE_B;

            // ---- S = Q @ K^T (3-term) ----
            float sacc[8][4];
#pragma unroll
            for (int i = 0; i < 8; i++)
#pragma unroll
                for (int c = 0; c < 4; c++) sacc[i][c] = 0.f;

#pragma unroll
            for (int kc = 0; kc < 4; kc++) {
#pragma unroll
                for (int np = 0; np < 4; np++) {
                    const int krow = np * 16 + b_row;
                    const uint32_t addr = aswz(krow, kc * 2 + b_coff);
                    uint32_t bh4[4], bl4[4];
                    ldsm_x4(bh4, sKh + addr);
                    ldsm_x4(bl4, sKl + addr);
#pragma unroll
                    for (int j = 0; j < 2; j++) {
                        float* d = sacc[2 * np + j];
                        mma16816(d, qfh[kc], &bh4[2 * j]);
                        mma16816(d, qfh[kc], &bl4[2 * j]);
                        mma16816(d, qfl[kc], &bh4[2 * j]);
                    }
                }
            }

            // ---- causal mask (global indices) ----
            if (need_mask) {
#pragma unroll
                for (int nt = 0; nt < 8; nt++) {
                    const int colg = tile_k0 + nt * 8 + kq;
                    if (colg > grow)         sacc[nt][0] = -INFINITY;
                    if (colg + 1 > grow)     sacc[nt][1] = -INFINITY;
                    if (colg > grow + 8)     sacc[nt][2] = -INFINITY;
                    if (colg + 1 > grow + 8) sacc[nt][3] = -INFINITY;
                }
            }

            // ---- online softmax (fragment layout) ----
            float rm0 = -INFINITY, rm1 = -INFINITY;
#pragma unroll
            for (int nt = 0; nt < 8; nt++) {
                rm0 = fmaxf(rm0, fmaxf(sacc[nt][0], sacc[nt][1]));
                rm1 = fmaxf(rm1, fmaxf(sacc[nt][2], sacc[nt][3]));
            }
            rm0 = fmaxf(rm0, __shfl_xor_sync(0xffffffffu, rm0, 1));
            rm0 = fmaxf(rm0, __shfl_xor_sync(0xffffffffu, rm0, 2));
            rm1 = fmaxf(rm1, __shfl_xor_sync(0xffffffffu, rm1, 1));
            rm1 = fmaxf(rm1, __shfl_xor_sync(0xffffffffu, rm1, 2));

            float mn0 = fmaxf(m0, rm0), mn1 = fmaxf(m1, rm1);
            float c0 = __expf(m0 - mn0), c1 = __expf(m1 - mn1);
            m0 = mn0; m1 = mn1;
            l0 *= c0; l1 *= c1;
#pragma unroll
            for (int nt = 0; nt < 8; nt++) {
                oa[nt][0] *= c0; oa[nt][1] *= c0;
                oa[nt][2] *= c1; oa[nt][3] *= c1;
            }

            // ---- P = exp(S - m), split + repack into A fragments ----
            uint32_t pfh[4][4], pfl[4][4];
            float ps0 = 0.f, ps1 = 0.f;
#pragma unroll
            for (int np = 0; np < 4; np++) {
#pragma unroll
                for (int j = 0; j < 2; j++) {
                    const int t = 2 * np + j;
                    float p0 = __expf(sacc[t][0] - m0);
                    float p1 = __expf(sacc[t][1] - m0);
                    float p2 = __expf(sacc[t][2] - m1);
                    float p3 = __expf(sacc[t][3] - m1);
                    ps0 += p0 + p1; ps1 += p2 + p3;
                    __nv_bfloat16 h0, e0, h1, e1, h2, e2, h3, e3;
                    split2(p0, h0, e0); split2(p1, h1, e1);
                    split2(p2, h2, e2); split2(p3, h3, e3);
                    pfh[np][2 * j]     = pack_bf2(h0, h1);
                    pfh[np][2 * j + 1] = pack_bf2(h2, h3);
                    pfl[np][2 * j]     = pack_bf2(e0, e1);
                    pfl[np][2 * j + 1] = pack_bf2(e2, e3);
                }
            }
            ps0 += __shfl_xor_sync(0xffffffffu, ps0, 1);
            ps0 += __shfl_xor_sync(0xffffffffu, ps0, 2);
            ps1 += __shfl_xor_sync(0xffffffffu, ps1, 1);
            ps1 += __shfl_xor_sync(0xffffffffu, ps1, 2);
            l0 += ps0; l1 += ps1;

            // ---- O += P @ V (3-term), V^T via ldmatrix.trans ----
#pragma unroll
            for (int kc2 = 0; kc2 < 4; kc2++) {
#pragma unroll
                for (int dp = 0; dp < 4; dp++) {
                    const int vrow = kc2 * 16 + (lane & 7) + ((vg & 1) << 3);
                    const uint32_t addr = aswz(vrow, dp * 2 + (vg >> 1));
                    uint32_t bvh[4], bvl[4];
                    ldsm_x4_t(bvh, sVh + addr);
                    ldsm_x4_t(bvl, sVl + addr);
#pragma unroll
                    for (int j = 0; j < 2; j++) {
                        float* d = oa[2 * dp + j];
                        mma16816(d, pfh[kc2], &bvh[2 * j]);
                        mma16816(d, pfl[kc2], &bvh[2 * j]);
                        mma16816(d, pfh[kc2], &bvl[2 * j]);
                    }
                }
            }
        }
    }

    // ---- epilogue: normalize, split, write [B*S, H*hd] bf16 hi/lo ----
    const float il0 = 1.0f / l0, il1 = 1.0f / l1;
    const int b = bh >> 4, h = bh & 15;
    const int s0 = qt * 128 + wid * 16 + (lane >> 2);
    const size_t mrow0 = (size_t)(b * SEQ + s0) * DMODEL + h * HD;
    const size_t mrow1 = mrow0 + 8 * DMODEL;
#pragma unroll
    for (int nt = 0; nt < 8; nt++) {
        const int d = nt * 8 + kq;
        __nv_bfloat16 h0, e0, h1, e1;
        split2(oa[nt][0] * il0, h0, e0);
        split2(oa[nt][1] * il0, h1, e1);
        *(uint32_t*)(outh + mrow0 + d) = pack_bf2(h0, h1);
        *(uint32_t*)(outl + mrow0 + d) = pack_bf2(e0, e1);
        split2(oa[nt][2] * il1, h0, e0);
        split2(oa[nt][3] * il1, h1, e1);
        *(uint32_t*)(outh + mrow1 + d) = pack_bf2(h0, h1);
        *(uint32_t*)(outl + mrow1 + d) = pack_bf2(e0, e1);
    }
}

// ---------------------------------------------------------------------------
extern "C" void kernel_launch(void* const* d_in, const int* in_sizes, int n_in,
                              void* d_out, int out_size)
{
    const float* x     = (const float*)d_in[0];
    const float* w_qkv = (const float*)d_in[1];
    const float* w_out = (const float*)d_in[2];
    float* out = (float*)d_out;

    __nv_bfloat16 *xh, *xl, *wqh, *wql, *woh, *wol, *ah, *al;
    __nv_bfloat16 *qh, *ql, *kh, *kl, *vh, *vl;
    float2* rope_tab;
    cudaGetSymbolAddress((void**)&xh,  g_xh);
    cudaGetSymbolAddress((void**)&xl,  g_xl);
    cudaGetSymbolAddress((void**)&wqh, g_wqh);
    cudaGetSymbolAddress((void**)&wql, g_wql);
    cudaGetSymbolAddress((void**)&woh, g_woh);
    cudaGetSymbolAddress((void**)&wol, g_wol);
    cudaGetSymbolAddress((void**)&ah,  g_ah);
    cudaGetSymbolAddress((void**)&al,  g_al);
    cudaGetSymbolAddress((void**)&qh,  g_qh);
    cudaGetSymbolAddress((void**)&ql,  g_ql);
    cudaGetSymbolAddress((void**)&kh,  g_kh);
    cudaGetSymbolAddress((void**)&kl,  g_kl);
    cudaGetSymbolAddress((void**)&vh,  g_vh);
    cudaGetSymbolAddress((void**)&vl,  g_vl);
    cudaGetSymbolAddress((void**)&rope_tab, g_rope_tab);

    cudaFuncSetAttribute(gemm_bf16x3_kernel,
                         cudaFuncAttributeMaxDynamicSharedMemorySize, G_SMEM_BYTES);
    cudaFuncSetAttribute(attn_tc_kernel,
                         cudaFuncAttributeMaxDynamicSharedMemorySize, AT_SMEM_B);

    // 1) rope table + convert inputs to split-bf16
    rope_table_kernel<<<(SEQ * 32) / 256, 256>>>(rope_tab);
    {
        int n = M_ROWS * DMODEL;
        convert_split_kernel<<<(n + 255) / 256, 256>>>(x, xh, xl, n);
    }
    transpose_split_kernel<<<dim3(QKV_N / 32, DMODEL / 32), dim3(32, 32)>>>(
        w_qkv, wqh, wql, DMODEL, QKV_N);
    transpose_split_kernel<<<dim3(DMODEL / 32, DMODEL / 32), dim3(32, 32)>>>(
        w_out, woh, wol, DMODEL, DMODEL);

    // 2) QKV projection + fused RoPE/split epilogue (tensor cores)
    gemm_bf16x3_kernel<<<dim3(QKV_N / 128, M_ROWS / 128), 256, G_SMEM_BYTES>>>(
        xh, xl, wqh, wql, nullptr, qh, ql, kh, kl, vh, vl,
        M_ROWS, QKV_N, DMODEL, 1);

    // 3) Tensor-core causal flash attention (writes out-proj A directly)
    attn_tc_kernel<<<dim3(SEQ / 128, BATCH * NH), 256, AT_SMEM_B>>>(
        qh, ql, kh, kl, vh, vl, ah, al);

    // 4) Output projection (tensor cores)
    gemm_bf16x3_kernel<<<dim3(DMODEL / 128, M_ROWS / 128), 256, G_SMEM_BYTES>>>(
        ah, al, woh, wol, out, nullptr, nullptr, nullptr, nullptr, nullptr, nullptr,
        M_ROWS, DMODEL, DMODEL, 0);
}

// round 11
// speedup vs baseline: 5.6875x; 1.4027x over previous
#include <cuda_runtime.h>
#include <cuda_fp16.h>
#include <math.h>
#include <stdint.h>

#define BATCH  2
#define SEQ    2048
#define DMODEL 1024
#define NH     16
#define HD     64
#define M_ROWS (BATCH * SEQ)    // 4096
#define QKV_N  (3 * DMODEL)     // 3072

// ---------------------------------------------------------------------------
// Device scratch (fp16 emulation: A-side split hi/lo, B-side hi only)
// ---------------------------------------------------------------------------
__device__ __half g_xh[M_ROWS * DMODEL];
__device__ __half g_xl[M_ROWS * DMODEL];
__device__ __half g_wqh[QKV_N * DMODEL];   // [N,K] transposed, hi only
__device__ __half g_woh[DMODEL * DMODEL];  // [N,K] transposed, hi only
__device__ __half g_ah[M_ROWS * DMODEL];   // attention out hi (A of out-proj)
__device__ __half g_al[M_ROWS * DMODEL];

#define QKV_ELEMS (BATCH * NH * SEQ * HD)
__device__ __half g_qh[QKV_ELEMS];  // [B,H,S,hd], pre-scaled by 1/8
__device__ __half g_ql[QKV_ELEMS];
__device__ __half g_kh[QKV_ELEMS];  // hi only (B operand of QK^T)
__device__ __half g_vh[QKV_ELEMS];  // hi only (B operand of PV)

__device__ float2 g_rope_tab[SEQ * 32];    // (cos, sin) per (s, j)

// ---------------------------------------------------------------------------
// Baseline-PTX helpers
// ---------------------------------------------------------------------------
__device__ __forceinline__ uint32_t smem_u32(const void* p) {
    uint32_t a;
    asm("{ .reg .u64 t; cvta.to.shared.u64 t, %1; cvt.u32.u64 %0, t; }"
        : "=r"(a) : "l"(p));
    return a;
}

#define CP_ASYNC_16(smem, gptr) \
    asm volatile("cp.async.cg.shared.global [%0], [%1], 16;\n" \
        :: "r"(smem), "l"(gptr))
#define CP_ASYNC_COMMIT() asm volatile("cp.async.commit_group;\n")
#define CP_ASYNC_WAIT(n)  asm volatile("cp.async.wait_group %0;\n" :: "n"(n))

__device__ __forceinline__ void ldsm_x4(uint32_t* r, uint32_t addr) {
    asm volatile("ldmatrix.sync.aligned.m8n8.x4.shared.b16 {%0,%1,%2,%3}, [%4];\n"
        : "=r"(r[0]), "=r"(r[1]), "=r"(r[2]), "=r"(r[3]) : "r"(addr));
}
__device__ __forceinline__ void ldsm_x4_t(uint32_t* r, uint32_t addr) {
    asm volatile("ldmatrix.sync.aligned.m8n8.x4.trans.shared.b16 {%0,%1,%2,%3}, [%4];\n"
        : "=r"(r[0]), "=r"(r[1]), "=r"(r[2]), "=r"(r[3]) : "r"(addr));
}

// D(f32) += A(f16) * B(f16): m16n8k16
__device__ __forceinline__ void mma16816(float* d, const uint32_t* a, const uint32_t* b) {
    asm volatile(
        "mma.sync.aligned.m16n8k16.row.col.f32.f16.f16.f32 "
        "{%0,%1,%2,%3}, {%4,%5,%6,%7}, {%8,%9}, {%0,%1,%2,%3};\n"
        : "+f"(d[0]), "+f"(d[1]), "+f"(d[2]), "+f"(d[3])
        : "r"(a[0]), "r"(a[1]), "r"(a[2]), "r"(a[3]), "r"(b[0]), "r"(b[1]));
}

// ---------------------------------------------------------------------------
// fp32 -> (hi, lo) fp16 split helpers
// ---------------------------------------------------------------------------
__device__ __forceinline__ void split2(float x, __half& h, __half& l) {
    h = __float2half(x);
    l = __float2half(x - __half2float(h));
}
__device__ __forceinline__ uint32_t pack_h2(__half a, __half b) {
    __half2 t; t.x = a; t.y = b;
    return *(uint32_t*)&t;
}

__global__ void rope_table_kernel(float2* tab) {
    int i = blockIdx.x * blockDim.x + threadIdx.x;   // < SEQ*32
    int j = i & 31, s = i >> 5;
    float inv_freq = powf(10000.0f, -(float)j * (1.0f / 32.0f));
    float sn, cs;
    sincosf((float)s * inv_freq, &sn, &cs);
    tab[i] = make_float2(cs, sn);
}

// Vectorized split: 4 elems/thread
__global__ void convert_split4_kernel(const float4* __restrict__ src,
                                      uint2* __restrict__ hi,
                                      uint2* __restrict__ lo, int n4) {
    int i = blockIdx.x * blockDim.x + threadIdx.x;
    if (i >= n4) return;
    float4 v = src[i];
    __half h0, l0, h1, l1, h2, l2, h3, l3;
    split2(v.x, h0, l0); split2(v.y, h1, l1);
    split2(v.z, h2, l2); split2(v.w, h3, l3);
    hi[i] = make_uint2(pack_h2(h0, h1), pack_h2(h2, h3));
    lo[i] = make_uint2(pack_h2(l0, l1), pack_h2(l2, l3));
}

// W[K,N] fp32 -> WT[N,K] fp16 hi only (tiled transpose)
__global__ void transpose_half_kernel(const float* __restrict__ W,
                                      __half* __restrict__ Th,
                                      int K, int N) {
    __shared__ float tile[32][33];
    int n = blockIdx.x * 32 + threadIdx.x;
    int k = blockIdx.y * 32 + threadIdx.y;
    tile[threadIdx.y][threadIdx.x] = W[(size_t)k * N + n];
    __syncthreads();
    int nt = blockIdx.x * 32 + threadIdx.y;
    int kt = blockIdx.y * 32 + threadIdx.x;
    Th[(size_t)nt * K + kt] = __float2half(tile[threadIdx.x][threadIdx.y]);
}

// ---------------------------------------------------------------------------
// Tensor-core GEMM: C = A@B, fp16 x 2-term fp32 emulation (A split, B hi).
// mode 0: store fp32 C.  mode 1: fused RoPE/split epilogue for QKV.
// ---------------------------------------------------------------------------
#define G_BK 32
#define G_TILE_B  (128 * 64)            // 8192
#define G_STAGE_B (3 * G_TILE_B)        // 24576: Ahi, Alo, Bh
#define G_STAGES  3
#define G_SMEM_BYTES (G_STAGES * G_STAGE_B)  // 73728

__device__ __forceinline__ uint32_t gswz(int row, int chunk) {
    return (uint32_t)(row * 64 + ((chunk ^ ((row >> 1) & 3)) << 4));
}

__global__ void __launch_bounds__(256)
gemm_fp16x2_kernel(const __half* __restrict__ Ahi,
                   const __half* __restrict__ Alo,
                   const __half* __restrict__ Bh,
                   float* __restrict__ C,
                   __half* __restrict__ qh, __half* __restrict__ ql,
                   __half* __restrict__ kh, __half* __restrict__ vh,
                   int M, int N, int K, int mode)
{
    extern __shared__ __align__(128) char dsm[];
    const uint32_t smem_base = smem_u32(dsm);

    const int tid = threadIdx.x;
    const int wid = tid >> 5;
    const int lane = tid & 31;
    const int warp_m = wid >> 1;
    const int warp_n = wid & 1;
    const int m0 = blockIdx.y * 128;
    const int n0 = blockIdx.x * 128;

    const __half* gsrc[3] = {Ahi, Alo, Bh};

    float acc[2][8][4];
#pragma unroll
    for (int i = 0; i < 2; i++)
#pragma unroll
        for (int j = 0; j < 8; j++)
#pragma unroll
            for (int c = 0; c < 4; c++) acc[i][j][c] = 0.f;

    const int nchunk = K / G_BK;

    auto issue = [&](int ci) {
        const int k0 = ci * G_BK;
        const uint32_t st = smem_base + (ci % G_STAGES) * G_STAGE_B;
#pragma unroll
        for (int i = 0; i < 6; i++) {
            const int tile = i >> 1;
            const int idx = ((i & 1) << 8) | tid;          // 0..511
            const int r = idx >> 2;                        // 0..127
            const int c = idx & 3;                         // 16B chunk
            const int grow = (tile < 2 ? m0 : n0) + r;
            const __half* gp = gsrc[tile] + (size_t)grow * K + k0 + c * 8;
            CP_ASYNC_16(st + tile * G_TILE_B + gswz(r, c), gp);
        }
        CP_ASYNC_COMMIT();
    };

    issue(0);
    issue(1);

    const int a_row_off = (lane & 15);
    const int a_coff    = (lane >> 4) & 1;
    const int b_row_off = ((lane & 16) >> 1) + (lane & 7);
    const int b_coff    = (lane & 8) >> 3;

#pragma unroll 1
    for (int ci = 0; ci < nchunk; ci++) {
        CP_ASYNC_WAIT(1);
        __syncthreads();
        if (ci + 2 < nchunk) issue(ci + 2);

        const uint32_t st = smem_base + (ci % G_STAGES) * G_STAGE_B;
        const uint32_t sAhi = st;
        const uint32_t sAlo = st + G_TILE_B;
        const uint32_t sBh  = st + 2 * G_TILE_B;

#pragma unroll
        for (int ks = 0; ks < 2; ks++) {
            uint32_t ahi[2][4], alo[2][4];
#pragma unroll
            for (int mt = 0; mt < 2; mt++) {
                const int ar = warp_m * 32 + mt * 16 + a_row_off;
                const uint32_t aoff = gswz(ar, ks * 2 + a_coff);
                ldsm_x4(ahi[mt], sAhi + aoff);
                ldsm_x4(alo[mt], sAlo + aoff);
            }
#pragma unroll
            for (int ntp = 0; ntp < 4; ntp++) {
                const int br = warp_n * 64 + ntp * 16 + b_row_off;
                const uint32_t boff = gswz(br, ks * 2 + b_coff);
                uint32_t bh4[4];
                ldsm_x4(bh4, sBh + boff);
#pragma unroll
                for (int mt = 0; mt < 2; mt++)
#pragma unroll
                    for (int j = 0; j < 2; j++) {
                        float* d = acc[mt][2 * ntp + j];
                        mma16816(d, ahi[mt], &bh4[2 * j]);
                        mma16816(d, alo[mt], &bh4[2 * j]);
                    }
            }
        }
    }

    const int quad = lane >> 2;
    const int tq = lane & 3;

    if (mode == 0) {
        float* Cw = C + (size_t)(m0 + warp_m * 32) * N + n0 + warp_n * 64;
#pragma unroll
        for (int mt = 0; mt < 2; mt++)
#pragma unroll
            for (int nt = 0; nt < 8; nt++) {
                const int r = mt * 16 + quad;
                const int c = nt * 8 + tq * 2;
                *(float2*)(Cw + (size_t)r * N + c) =
                    make_float2(acc[mt][nt][0], acc[mt][nt][1]);
                *(float2*)(Cw + (size_t)(r + 8) * N + c) =
                    make_float2(acc[mt][nt][2], acc[mt][nt][3]);
            }
        return;
    }

    // ---- mode 1: fused RoPE + split epilogue for QKV ----
    const int ng0 = n0 + warp_n * 64;          // 64-aligned -> single head
    const int sec = ng0 >> 10;                 // 0=q, 1=k, 2=v
    const int hh  = (ng0 & 1023) >> 6;
    __half* ph = (sec == 0) ? qh : (sec == 1) ? kh : vh;

#pragma unroll
    for (int mt = 0; mt < 2; mt++) {
#pragma unroll
        for (int half = 0; half < 2; half++) {
            const int r_g = m0 + warp_m * 32 + mt * 16 + quad + half * 8;
            const int b = r_g >> 11, s = r_g & 2047;
            const size_t dst = ((size_t)((b * NH + hh) * SEQ) + s) * HD;
            const float2* trow = g_rope_tab + s * 32;
#pragma unroll
            for (int nt = 0; nt < 8; nt++) {
                const int d0 = nt * 8 + tq * 2;
                float v0 = acc[mt][nt][half * 2 + 0];
                float v1 = acc[mt][nt][half * 2 + 1];
                float r0, r1;
                if (sec < 2) {
                    const float p0 = acc[mt][nt ^ 4][half * 2 + 0];
                    const float p1 = acc[mt][nt ^ 4][half * 2 + 1];
                    const int j0 = d0 & 31;
                    const float2 t0 = trow[j0];
                    const float2 t1 = trow[j0 + 1];
                    if (nt < 4) { r0 = v0 * t0.x - p0 * t0.y; r1 = v1 * t1.x - p1 * t1.y; }
                    else        { r0 = v0 * t0.x + p0 * t0.y; r1 = v1 * t1.x + p1 * t1.y; }
                    if (sec == 0) { r0 *= 0.125f; r1 *= 0.125f; }
                } else { r0 = v0; r1 = v1; }
                if (sec == 0) {
                    __half h0, e0, h1, e1;
                    split2(r0, h0, e0);
                    split2(r1, h1, e1);
                    *(uint32_t*)(qh + dst + d0) = pack_h2(h0, h1);
                    *(uint32_t*)(ql + dst + d0) = pack_h2(e0, e1);
                } else {
                    *(uint32_t*)(ph + dst + d0) =
                        pack_h2(__float2half(r0), __float2half(r1));
                }
            }
        }
    }
}

// ---------------------------------------------------------------------------
// Tensor-core causal flash attention (fp16 x 2-term emulation).
// 256 threads = 8 warps, q-tile 128 (16 rows/warp). Key tiles of 64.
// K/V single fp16 tiles (hi only) -> 16KB/stage, double-buffered (32KB).
// ---------------------------------------------------------------------------
#define AT_TILE_B  (64 * 128)             // 8192
#define AT_STAGE_B (2 * AT_TILE_B)        // 16384: Kh, Vh
#define AT_SMEM_B  (2 * AT_STAGE_B)       // 32768

__device__ __forceinline__ uint32_t aswz(int row, int chunk) {
    return (uint32_t)(row * 128 + ((chunk ^ (row & 7)) << 4));
}

__global__ void __launch_bounds__(256)
attn_tc_kernel(const __half* __restrict__ qh, const __half* __restrict__ ql,
               const __half* __restrict__ kh, const __half* __restrict__ vh,
               __half* __restrict__ outh, __half* __restrict__ outl)
{
    extern __shared__ __align__(128) char dsm[];
    const uint32_t sb = smem_u32(dsm);

    const int bh = blockIdx.y;
    const int qt = gridDim.x - 1 - blockIdx.x;   // heavy q-tiles first
    const int tid = threadIdx.x;
    const int wid = tid >> 5;
    const int lane = tid & 31;
    const int kq = (lane & 3) * 2;               // fragment col offset
    const size_t base = (size_t)bh * SEQ * HD;

    const __half* khp = kh + base;
    const __half* vhp = vh + base;

    // ---- Q fragments (register resident) ----
    const int rloc = wid * 16 + (lane >> 2);     // local q row, +8 pair
    const int grow = qt * 128 + rloc;            // global q row
    uint32_t qfh[4][4], qfl[4][4];
#pragma unroll
    for (int kc = 0; kc < 4; kc++) {
        size_t o = base + (size_t)grow * HD + kc * 16 + kq;
        qfh[kc][0] = *(const uint32_t*)(qh + o);
        qfh[kc][1] = *(const uint32_t*)(qh + o + 8 * HD);
        qfh[kc][2] = *(const uint32_t*)(qh + o + 8);
        qfh[kc][3] = *(const uint32_t*)(qh + o + 8 * HD + 8);
        qfl[kc][0] = *(const uint32_t*)(ql + o);
        qfl[kc][1] = *(const uint32_t*)(ql + o + 8 * HD);
        qfl[kc][2] = *(const uint32_t*)(ql + o + 8);
        qfl[kc][3] = *(const uint32_t*)(ql + o + 8 * HD + 8);
    }

    float oa[8][4];
#pragma unroll
    for (int i = 0; i < 8; i++)
#pragma unroll
        for (int c = 0; c < 4; c++) oa[i][c] = 0.f;
    float m0 = -INFINITY, m1 = -INFINITY, l0 = 0.f, l1 = 0.f;

    auto issue = [&](int kt) {
        const uint32_t st = sb + (kt & 1) * AT_STAGE_B;
        const __half* srcs[2] = {khp, vhp};
        const int kr0 = kt * 64;
#pragma unroll
        for (int t = 0; t < 2; t++) {
#pragma unroll
            for (int i = 0; i < 2; i++) {
                int c = i * 256 + tid;           // 0..511
                int row = c >> 3, col = c & 7;
                CP_ASYNC_16(st + t * AT_TILE_B + aswz(row, col),
                            srcs[t] + (size_t)(kr0 + row) * HD + col * 8);
            }
        }
        CP_ASYNC_COMMIT();
    };

    issue(0);

    const int b_row = ((lane & 16) >> 1) + (lane & 7);
    const int b_coff = (lane & 8) >> 3;
    const int vg    = lane >> 3;

    const int nkt = 2 * qt + 2;                  // key tiles: 0 .. 2qt+1

#pragma unroll 1
    for (int kt = 0; kt < nkt; kt++) {
        CP_ASYNC_WAIT(0);
        __syncthreads();
        if (kt + 1 < nkt) issue(kt + 1);

        const int tile_k0 = kt * 64;
        const int wrow_min = qt * 128 + wid * 16;
        const bool full_skip = tile_k0 > wrow_min + 15;
        const bool need_mask = !full_skip && (tile_k0 + 63 > wrow_min);

        if (!full_skip) {
            const uint32_t st  = sb + (kt & 1) * AT_STAGE_B;
            const uint32_t sKh = st;
            const uint32_t sVh = st + AT_TILE_B;

            // ---- S = Q @ K^T (2-term) ----
            float sacc[8][4];
#pragma unroll
            for (int i = 0; i < 8; i++)
#pragma unroll
                for (int c = 0; c < 4; c++) sacc[i][c] = 0.f;

#pragma unroll
            for (int kc = 0; kc < 4; kc++) {
#pragma unroll
                for (int np = 0; np < 4; np++) {
                    const int krow = np * 16 + b_row;
                    const uint32_t addr = aswz(krow, kc * 2 + b_coff);
                    uint32_t bh4[4];
                    ldsm_x4(bh4, sKh + addr);
#pragma unroll
                    for (int j = 0; j < 2; j++) {
                        float* d = sacc[2 * np + j];
                        mma16816(d, qfh[kc], &bh4[2 * j]);
                        mma16816(d, qfl[kc], &bh4[2 * j]);
                    }
                }
            }

            // ---- causal mask (global indices) ----
            if (need_mask) {
#pragma unroll
                for (int nt = 0; nt < 8; nt++) {
                    const int colg = tile_k0 + nt * 8 + kq;
                    if (colg > grow)         sacc[nt][0] = -INFINITY;
                    if (colg + 1 > grow)     sacc[nt][1] = -INFINITY;
                    if (colg > grow + 8)     sacc[nt][2] = -INFINITY;
                    if (colg + 1 > grow + 8) sacc[nt][3] = -INFINITY;
                }
            }

            // ---- online softmax ----
            float rm0 = -INFINITY, rm1 = -INFINITY;
#pragma unroll
            for (int nt = 0; nt < 8; nt++) {
                rm0 = fmaxf(rm0, fmaxf(sacc[nt][0], sacc[nt][1]));
                rm1 = fmaxf(rm1, fmaxf(sacc[nt][2], sacc[nt][3]));
            }
            rm0 = fmaxf(rm0, __shfl_xor_sync(0xffffffffu, rm0, 1));
            rm0 = fmaxf(rm0, __shfl_xor_sync(0xffffffffu, rm0, 2));
            rm1 = fmaxf(rm1, __shfl_xor_sync(0xffffffffu, rm1, 1));
            rm1 = fmaxf(rm1, __shfl_xor_sync(0xffffffffu, rm1, 2));

            float mn0 = fmaxf(m0, rm0), mn1 = fmaxf(m1, rm1);
            float c0 = __expf(m0 - mn0), c1 = __expf(m1 - mn1);
            m0 = mn0; m1 = mn1;
            l0 *= c0; l1 *= c1;
#pragma unroll
            for (int nt = 0; nt < 8; nt++) {
                oa[nt][0] *= c0; oa[nt][1] *= c0;
                oa[nt][2] *= c1; oa[nt][3] *= c1;
            }

            // ---- P = exp(S - m) built per 16-key group; O += P @ V (2-term) ----
            float ps0 = 0.f, ps1 = 0.f;
#pragma unroll
            for (int kc2 = 0; kc2 < 4; kc2++) {
                uint32_t pfh[4], pfl[4];
#pragma unroll
                for (int j = 0; j < 2; j++) {
                    const int t = 2 * kc2 + j;
                    float p0 = __expf(sacc[t][0] - m0);
                    float p1 = __expf(sacc[t][1] - m0);
                    float p2 = __expf(sacc[t][2] - m1);
                    float p3 = __expf(sacc[t][3] - m1);
                    ps0 += p0 + p1; ps1 += p2 + p3;
                    __half h0, e0, h1, e1, h2, e2, h3, e3;
                    split2(p0, h0, e0); split2(p1, h1, e1);
                    split2(p2, h2, e2); split2(p3, h3, e3);
                    pfh[2 * j]     = pack_h2(h0, h1);
                    pfh[2 * j + 1] = pack_h2(h2, h3);
                    pfl[2 * j]     = pack_h2(e0, e1);
                    pfl[2 * j + 1] = pack_h2(e2, e3);
                }
#pragma unroll
                for (int dp = 0; dp < 4; dp++) {
                    const int vrow = kc2 * 16 + (lane & 7) + ((vg & 1) << 3);
                    const uint32_t addr = aswz(vrow, dp * 2 + (vg >> 1));
                    uint32_t bvh[4];
                    ldsm_x4_t(bvh, sVh + addr);
#pragma unroll
                    for (int j = 0; j < 2; j++) {
                        float* d = oa[2 * dp + j];
                        mma16816(d, pfh, &bvh[2 * j]);
                        mma16816(d, pfl, &bvh[2 * j]);
                    }
                }
            }
            ps0 += __shfl_xor_sync(0xffffffffu, ps0, 1);
            ps0 += __shfl_xor_sync(0xffffffffu, ps0, 2);
            ps1 += __shfl_xor_sync(0xffffffffu, ps1, 1);
            ps1 += __shfl_xor_sync(0xffffffffu, ps1, 2);
            l0 += ps0; l1 += ps1;
        }
    }

    // ---- epilogue: normalize, split, write [B*S, H*hd] fp16 hi/lo ----
    const float il0 = 1.0f / l0, il1 = 1.0f / l1;
    const int b = bh >> 4, h = bh & 15;
    const int s0 = qt * 128 + wid * 16 + (lane >> 2);
    const size_t mrow0 = (size_t)(b * SEQ + s0) * DMODEL + h * HD;
    const size_t mrow1 = mrow0 + 8 * DMODEL;
#pragma unroll
    for (int nt = 0; nt < 8; nt++) {
        const int d = nt * 8 + kq;
        __half h0, e0, h1, e1;
        split2(oa[nt][0] * il0, h0, e0);
        split2(oa[nt][1] * il0, h1, e1);
        *(uint32_t*)(outh + mrow0 + d) = pack_h2(h0, h1);
        *(uint32_t*)(outl + mrow0 + d) = pack_h2(e0, e1);
        split2(oa[nt][2] * il1, h0, e0);
        split2(oa[nt][3] * il1, h1, e1);
        *(uint32_t*)(outh + mrow1 + d) = pack_h2(h0, h1);
        *(uint32_t*)(outl + mrow1 + d) = pack_h2(e0, e1);
    }
}

// ---------------------------------------------------------------------------
extern "C" void kernel_launch(void* const* d_in, const int* in_sizes, int n_in,
                              void* d_out, int out_size)
{
    const float* x     = (const float*)d_in[0];
    const float* w_qkv = (const float*)d_in[1];
    const float* w_out = (const float*)d_in[2];
    float* out = (float*)d_out;

    __half *xh, *xl, *wqh, *woh, *ah, *al, *qh, *ql, *kh, *vh;
    float2* rope_tab;
    cudaGetSymbolAddress((void**)&xh,  g_xh);
    cudaGetSymbolAddress((void**)&xl,  g_xl);
    cudaGetSymbolAddress((void**)&wqh, g_wqh);
    cudaGetSymbolAddress((void**)&woh, g_woh);
    cudaGetSymbolAddress((void**)&ah,  g_ah);
    cudaGetSymbolAddress((void**)&al,  g_al);
    cudaGetSymbolAddress((void**)&qh,  g_qh);
    cudaGetSymbolAddress((void**)&ql,  g_ql);
    cudaGetSymbolAddress((void**)&kh,  g_kh);
    cudaGetSymbolAddress((void**)&vh,  g_vh);
    cudaGetSymbolAddress((void**)&rope_tab, g_rope_tab);

    cudaFuncSetAttribute(gemm_fp16x2_kernel,
                         cudaFuncAttributeMaxDynamicSharedMemorySize, G_SMEM_BYTES);
    cudaFuncSetAttribute(attn_tc_kernel,
                         cudaFuncAttributeMaxDynamicSharedMemorySize, AT_SMEM_B);

    // 1) rope table + convert inputs
    rope_table_kernel<<<(SEQ * 32) / 256, 256>>>(rope_tab);
    {
        int n4 = M_ROWS * DMODEL / 4;
        convert_split4_kernel<<<(n4 + 255) / 256, 256>>>(
            (const float4*)x, (uint2*)xh, (uint2*)xl, n4);
    }
    transpose_half_kernel<<<dim3(QKV_N / 32, DMODEL / 32), dim3(32, 32)>>>(
        w_qkv, wqh, DMODEL, QKV_N);
    transpose_half_kernel<<<dim3(DMODEL / 32, DMODEL / 32), dim3(32, 32)>>>(
        w_out, woh, DMODEL, DMODEL);

    // 2) QKV projection + fused RoPE/split epilogue (tensor cores)
    gemm_fp16x2_kernel<<<dim3(QKV_N / 128, M_ROWS / 128), 256, G_SMEM_BYTES>>>(
        xh, xl, wqh, nullptr, qh, ql, kh, vh, M_ROWS, QKV_N, DMODEL, 1);

    // 3) Tensor-core causal flash attention (writes out-proj A directly)
    attn_tc_kernel<<<dim3(SEQ / 128, BATCH * NH), 256, AT_SMEM_B>>>(
        qh, ql, kh, vh, ah, al);

    // 4) Output projection (tensor cores)
    gemm_fp16x2_kernel<<<dim3(DMODEL / 128, M_ROWS / 128), 256, G_SMEM_BYTES>>>(
        ah, al, woh, out, nullptr, nullptr, nullptr, nullptr,
        M_ROWS, DMODEL, DMODEL, 0);
}

// round 12
// speedup vs baseline: 5.8676x; 1.0317x over previous
#include <cuda_runtime.h>
#include <cuda_fp16.h>
#include <math.h>
#include <stdint.h>

#define BATCH  2
#define SEQ    2048
#define DMODEL 1024
#define NH     16
#define HD     64
#define M_ROWS (BATCH * SEQ)    // 4096
#define QKV_N  (3 * DMODEL)     // 3072

// ---------------------------------------------------------------------------
// Device scratch (fp16 emulation: A-side split hi/lo, B-side hi only)
// ---------------------------------------------------------------------------
__device__ __half g_xh[M_ROWS * DMODEL];
__device__ __half g_xl[M_ROWS * DMODEL];
__device__ __half g_wqh[QKV_N * DMODEL];   // [N,K] transposed, hi only
__device__ __half g_woh[DMODEL * DMODEL];  // [N,K] transposed, hi only
__device__ __half g_ah[M_ROWS * DMODEL];   // attention out hi (A of out-proj)
__device__ __half g_al[M_ROWS * DMODEL];

#define QKV_ELEMS (BATCH * NH * SEQ * HD)
__device__ __half g_qh[QKV_ELEMS];  // [B,H,S,hd], pre-scaled by 1/8
__device__ __half g_ql[QKV_ELEMS];
__device__ __half g_kh[QKV_ELEMS];  // hi only (B operand of QK^T)
__device__ __half g_vh[QKV_ELEMS];  // hi only (B operand of PV)

__device__ float2 g_rope_tab[SEQ * 32];    // (cos, sin) per (s, j)

// ---------------------------------------------------------------------------
// Baseline-PTX helpers
// ---------------------------------------------------------------------------
__device__ __forceinline__ uint32_t smem_u32(const void* p) {
    uint32_t a;
    asm("{ .reg .u64 t; cvta.to.shared.u64 t, %1; cvt.u32.u64 %0, t; }"
        : "=r"(a) : "l"(p));
    return a;
}

#define CP_ASYNC_16(smem, gptr) \
    asm volatile("cp.async.cg.shared.global [%0], [%1], 16;\n" \
        :: "r"(smem), "l"(gptr))
#define CP_ASYNC_COMMIT() asm volatile("cp.async.commit_group;\n")
#define CP_ASYNC_WAIT(n)  asm volatile("cp.async.wait_group %0;\n" :: "n"(n))

__device__ __forceinline__ void ldsm_x4(uint32_t* r, uint32_t addr) {
    asm volatile("ldmatrix.sync.aligned.m8n8.x4.shared.b16 {%0,%1,%2,%3}, [%4];\n"
        : "=r"(r[0]), "=r"(r[1]), "=r"(r[2]), "=r"(r[3]) : "r"(addr));
}
__device__ __forceinline__ void ldsm_x4_t(uint32_t* r, uint32_t addr) {
    asm volatile("ldmatrix.sync.aligned.m8n8.x4.trans.shared.b16 {%0,%1,%2,%3}, [%4];\n"
        : "=r"(r[0]), "=r"(r[1]), "=r"(r[2]), "=r"(r[3]) : "r"(addr));
}

// D(f32) += A(f16) * B(f16): m16n8k16
__device__ __forceinline__ void mma16816(float* d, const uint32_t* a, const uint32_t* b) {
    asm volatile(
        "mma.sync.aligned.m16n8k16.row.col.f32.f16.f16.f32 "
        "{%0,%1,%2,%3}, {%4,%5,%6,%7}, {%8,%9}, {%0,%1,%2,%3};\n"
        : "+f"(d[0]), "+f"(d[1]), "+f"(d[2]), "+f"(d[3])
        : "r"(a[0]), "r"(a[1]), "r"(a[2]), "r"(a[3]), "r"(b[0]), "r"(b[1]));
}

// ---------------------------------------------------------------------------
// fp32 -> (hi, lo) fp16 split helpers
// ---------------------------------------------------------------------------
__device__ __forceinline__ void split2(float x, __half& h, __half& l) {
    h = __float2half(x);
    l = __float2half(x - __half2float(h));
}
__device__ __forceinline__ uint32_t pack_h2(__half a, __half b) {
    __half2 t; t.x = a; t.y = b;
    return *(uint32_t*)&t;
}

__global__ void rope_table_kernel(float2* tab) {
    int i = blockIdx.x * blockDim.x + threadIdx.x;   // < SEQ*32
    int j = i & 31, s = i >> 5;
    float inv_freq = powf(10000.0f, -(float)j * (1.0f / 32.0f));
    float sn, cs;
    sincosf((float)s * inv_freq, &sn, &cs);
    tab[i] = make_float2(cs, sn);
}

// Vectorized split: 4 elems/thread
__global__ void convert_split4_kernel(const float4* __restrict__ src,
                                      uint2* __restrict__ hi,
                                      uint2* __restrict__ lo, int n4) {
    int i = blockIdx.x * blockDim.x + threadIdx.x;
    if (i >= n4) return;
    float4 v = src[i];
    __half h0, l0, h1, l1, h2, l2, h3, l3;
    split2(v.x, h0, l0); split2(v.y, h1, l1);
    split2(v.z, h2, l2); split2(v.w, h3, l3);
    hi[i] = make_uint2(pack_h2(h0, h1), pack_h2(h2, h3));
    lo[i] = make_uint2(pack_h2(l0, l1), pack_h2(l2, l3));
}

// Both weight transposes in one launch. n in [0,4096): <3072 -> w_qkv, else w_out.
__global__ void transpose_both_kernel(const float* __restrict__ Wq,
                                      const float* __restrict__ Wo,
                                      __half* __restrict__ Tq,
                                      __half* __restrict__ To) {
    __shared__ float tile[32][33];
    int n = blockIdx.x * 32 + threadIdx.x;
    int k = blockIdx.y * 32 + threadIdx.y;
    float v = (n < QKV_N) ? Wq[(size_t)k * QKV_N + n]
                          : Wo[(size_t)k * DMODEL + (n - QKV_N)];
    tile[threadIdx.y][threadIdx.x] = v;
    __syncthreads();
    int nt = blockIdx.x * 32 + threadIdx.y;
    int kt = blockIdx.y * 32 + threadIdx.x;
    __half hv = __float2half(tile[threadIdx.x][threadIdx.y]);
    if (nt < QKV_N) Tq[(size_t)nt * DMODEL + kt] = hv;
    else            To[(size_t)(nt - QKV_N) * DMODEL + kt] = hv;
}

// ---------------------------------------------------------------------------
// Tensor-core GEMM: C = A@B, fp16 x 2-term fp32 emulation (A split, B hi).
// mode 0: store fp32 C.  mode 1: fused RoPE/split epilogue for QKV.
// ---------------------------------------------------------------------------
#define G_BK 32
#define G_TILE_B  (128 * 64)            // 8192
#define G_STAGE_B (3 * G_TILE_B)        // 24576: Ahi, Alo, Bh
#define G_STAGES  3
#define G_SMEM_BYTES (G_STAGES * G_STAGE_B)  // 73728

__device__ __forceinline__ uint32_t gswz(int row, int chunk) {
    return (uint32_t)(row * 64 + ((chunk ^ ((row >> 1) & 3)) << 4));
}

__global__ void __launch_bounds__(256)
gemm_fp16x2_kernel(const __half* __restrict__ Ahi,
                   const __half* __restrict__ Alo,
                   const __half* __restrict__ Bh,
                   float* __restrict__ C,
                   __half* __restrict__ qh, __half* __restrict__ ql,
                   __half* __restrict__ kh, __half* __restrict__ vh,
                   int M, int N, int K, int mode)
{
    extern __shared__ __align__(128) char dsm[];
    const uint32_t smem_base = smem_u32(dsm);

    const int tid = threadIdx.x;
    const int wid = tid >> 5;
    const int lane = tid & 31;
    const int warp_m = wid >> 1;
    const int warp_n = wid & 1;
    const int m0 = blockIdx.y * 128;
    const int n0 = blockIdx.x * 128;

    const __half* gsrc[3] = {Ahi, Alo, Bh};

    float acc[2][8][4];
#pragma unroll
    for (int i = 0; i < 2; i++)
#pragma unroll
        for (int j = 0; j < 8; j++)
#pragma unroll
            for (int c = 0; c < 4; c++) acc[i][j][c] = 0.f;

    const int nchunk = K / G_BK;

    auto issue = [&](int ci) {
        const int k0 = ci * G_BK;
        const uint32_t st = smem_base + (ci % G_STAGES) * G_STAGE_B;
#pragma unroll
        for (int i = 0; i < 6; i++) {
            const int tile = i >> 1;
            const int idx = ((i & 1) << 8) | tid;          // 0..511
            const int r = idx >> 2;                        // 0..127
            const int c = idx & 3;                         // 16B chunk
            const int grow = (tile < 2 ? m0 : n0) + r;
            const __half* gp = gsrc[tile] + (size_t)grow * K + k0 + c * 8;
            CP_ASYNC_16(st + tile * G_TILE_B + gswz(r, c), gp);
        }
        CP_ASYNC_COMMIT();
    };

    issue(0);
    issue(1);

    const int a_row_off = (lane & 15);
    const int a_coff    = (lane >> 4) & 1;
    const int b_row_off = ((lane & 16) >> 1) + (lane & 7);
    const int b_coff    = (lane & 8) >> 3;

#pragma unroll 1
    for (int ci = 0; ci < nchunk; ci++) {
        CP_ASYNC_WAIT(1);
        __syncthreads();
        if (ci + 2 < nchunk) issue(ci + 2);

        const uint32_t st = smem_base + (ci % G_STAGES) * G_STAGE_B;
        const uint32_t sAhi = st;
        const uint32_t sAlo = st + G_TILE_B;
        const uint32_t sBh  = st + 2 * G_TILE_B;

#pragma unroll
        for (int ks = 0; ks < 2; ks++) {
            uint32_t ahi[2][4], alo[2][4];
#pragma unroll
            for (int mt = 0; mt < 2; mt++) {
                const int ar = warp_m * 32 + mt * 16 + a_row_off;
                const uint32_t aoff = gswz(ar, ks * 2 + a_coff);
                ldsm_x4(ahi[mt], sAhi + aoff);
                ldsm_x4(alo[mt], sAlo + aoff);
            }
#pragma unroll
            for (int ntp = 0; ntp < 4; ntp++) {
                const int br = warp_n * 64 + ntp * 16 + b_row_off;
                const uint32_t boff = gswz(br, ks * 2 + b_coff);
                uint32_t bh4[4];
                ldsm_x4(bh4, sBh + boff);
#pragma unroll
                for (int mt = 0; mt < 2; mt++)
#pragma unroll
                    for (int j = 0; j < 2; j++) {
                        float* d = acc[mt][2 * ntp + j];
                        mma16816(d, ahi[mt], &bh4[2 * j]);
                        mma16816(d, alo[mt], &bh4[2 * j]);
                    }
            }
        }
    }

    const int quad = lane >> 2;
    const int tq = lane & 3;

    if (mode == 0) {
        float* Cw = C + (size_t)(m0 + warp_m * 32) * N + n0 + warp_n * 64;
#pragma unroll
        for (int mt = 0; mt < 2; mt++)
#pragma unroll
            for (int nt = 0; nt < 8; nt++) {
                const int r = mt * 16 + quad;
                const int c = nt * 8 + tq * 2;
                *(float2*)(Cw + (size_t)r * N + c) =
                    make_float2(acc[mt][nt][0], acc[mt][nt][1]);
                *(float2*)(Cw + (size_t)(r + 8) * N + c) =
                    make_float2(acc[mt][nt][2], acc[mt][nt][3]);
            }
        return;
    }

    // ---- mode 1: fused RoPE + split epilogue for QKV ----
    const int ng0 = n0 + warp_n * 64;          // 64-aligned -> single head
    const int sec = ng0 >> 10;                 // 0=q, 1=k, 2=v
    const int hh  = (ng0 & 1023) >> 6;
    __half* ph = (sec == 0) ? qh : (sec == 1) ? kh : vh;

#pragma unroll
    for (int mt = 0; mt < 2; mt++) {
#pragma unroll
        for (int half = 0; half < 2; half++) {
            const int r_g = m0 + warp_m * 32 + mt * 16 + quad + half * 8;
            const int b = r_g >> 11, s = r_g & 2047;
            const size_t dst = ((size_t)((b * NH + hh) * SEQ) + s) * HD;
            const float2* trow = g_rope_tab + s * 32;
#pragma unroll
            for (int nt = 0; nt < 8; nt++) {
                const int d0 = nt * 8 + tq * 2;
                float v0 = acc[mt][nt][half * 2 + 0];
                float v1 = acc[mt][nt][half * 2 + 1];
                float r0, r1;
                if (sec < 2) {
                    const float p0 = acc[mt][nt ^ 4][half * 2 + 0];
                    const float p1 = acc[mt][nt ^ 4][half * 2 + 1];
                    const int j0 = d0 & 31;
                    const float2 t0 = trow[j0];
                    const float2 t1 = trow[j0 + 1];
                    if (nt < 4) { r0 = v0 * t0.x - p0 * t0.y; r1 = v1 * t1.x - p1 * t1.y; }
                    else        { r0 = v0 * t0.x + p0 * t0.y; r1 = v1 * t1.x + p1 * t1.y; }
                    if (sec == 0) { r0 *= 0.125f; r1 *= 0.125f; }
                } else { r0 = v0; r1 = v1; }
                if (sec == 0) {
                    __half h0, e0, h1, e1;
                    split2(r0, h0, e0);
                    split2(r1, h1, e1);
                    *(uint32_t*)(qh + dst + d0) = pack_h2(h0, h1);
                    *(uint32_t*)(ql + dst + d0) = pack_h2(e0, e1);
                } else {
                    *(uint32_t*)(ph + dst + d0) =
                        pack_h2(__float2half(r0), __float2half(r1));
                }
            }
        }
    }
}

// ---------------------------------------------------------------------------
// Tensor-core causal flash attention (fp16 x 2-term emulation).
// 256 threads = 8 warps, q-tile 128 (16 rows/warp). Key tiles of 64.
// Q-tile pairing: block bx processes q-tiles {15-bx, bx} -> uniform 34
// key-tile units per block, near-single-wave. 3-stage cp.async pipeline.
// ---------------------------------------------------------------------------
#define AT_TILE_B  (64 * 128)             // 8192
#define AT_STAGE_B (2 * AT_TILE_B)        // 16384: Kh, Vh
#define AT_STAGES  3
#define AT_SMEM_B  (AT_STAGES * AT_STAGE_B)  // 49152

__device__ __forceinline__ uint32_t aswz(int row, int chunk) {
    return (uint32_t)(row * 128 + ((chunk ^ (row & 7)) << 4));
}

__global__ void __launch_bounds__(256)
attn_tc_kernel(const __half* __restrict__ qh, const __half* __restrict__ ql,
               const __half* __restrict__ kh, const __half* __restrict__ vh,
               __half* __restrict__ outh, __half* __restrict__ outl)
{
    extern __shared__ __align__(128) char dsm[];
    const uint32_t sb = smem_u32(dsm);

    const int bh = blockIdx.y;
    const int tid = threadIdx.x;
    const int wid = tid >> 5;
    const int lane = tid & 31;
    const int kq = (lane & 3) * 2;               // fragment col offset
    const size_t base = (size_t)bh * SEQ * HD;

    const __half* khp = kh + base;
    const __half* vhp = vh + base;

    auto issue = [&](int kt) {
        const uint32_t st = sb + (kt % AT_STAGES) * AT_STAGE_B;
        const __half* srcs[2] = {khp, vhp};
        const int kr0 = kt * 64;
#pragma unroll
        for (int t = 0; t < 2; t++) {
#pragma unroll
            for (int i = 0; i < 2; i++) {
                int c = i * 256 + tid;           // 0..511
                int row = c >> 3, col = c & 7;
                CP_ASYNC_16(st + t * AT_TILE_B + aswz(row, col),
                            srcs[t] + (size_t)(kr0 + row) * HD + col * 8);
            }
        }
        CP_ASYNC_COMMIT();
    };

    const int b_row = ((lane & 16) >> 1) + (lane & 7);
    const int b_coff = (lane & 8) >> 3;
    const int vg    = lane >> 3;
    const int rloc = wid * 16 + (lane >> 2);     // local q row, +8 pair

#pragma unroll 1
    for (int ps = 0; ps < 2; ps++) {
        const int qt = ps ? (int)blockIdx.x : (SEQ / 128 - 1 - (int)blockIdx.x);
        const int grow = qt * 128 + rloc;        // global q row

        // ---- Q fragments (register resident) ----
        uint32_t qfh[4][4], qfl[4][4];
#pragma unroll
        for (int kc = 0; kc < 4; kc++) {
            size_t o = base + (size_t)grow * HD + kc * 16 + kq;
            qfh[kc][0] = *(const uint32_t*)(qh + o);
            qfh[kc][1] = *(const uint32_t*)(qh + o + 8 * HD);
            qfh[kc][2] = *(const uint32_t*)(qh + o + 8);
            qfh[kc][3] = *(const uint32_t*)(qh + o + 8 * HD + 8);
            qfl[kc][0] = *(const uint32_t*)(ql + o);
            qfl[kc][1] = *(const uint32_t*)(ql + o + 8 * HD);
            qfl[kc][2] = *(const uint32_t*)(ql + o + 8);
            qfl[kc][3] = *(const uint32_t*)(ql + o + 8 * HD + 8);
        }

        float oa[8][4];
#pragma unroll
        for (int i = 0; i < 8; i++)
#pragma unroll
            for (int c = 0; c < 4; c++) oa[i][c] = 0.f;
        float m0 = -INFINITY, m1 = -INFINITY, l0 = 0.f, l1 = 0.f;

        const int nkt = 2 * qt + 2;              // key tiles: 0 .. 2qt+1

        __syncthreads();                         // smem safe for reuse
        issue(0);
        if (nkt > 1) issue(1);

#pragma unroll 1
        for (int kt = 0; kt < nkt; kt++) {
            if (kt + 1 < nkt) { CP_ASYNC_WAIT(1); } else { CP_ASYNC_WAIT(0); }
            __syncthreads();
            if (kt + 2 < nkt) issue(kt + 2);

            const int tile_k0 = kt * 64;
            const int wrow_min = qt * 128 + wid * 16;
            const bool full_skip = tile_k0 > wrow_min + 15;
            const bool need_mask = !full_skip && (tile_k0 + 63 > wrow_min);

            if (!full_skip) {
                const uint32_t st  = sb + (kt % AT_STAGES) * AT_STAGE_B;
                const uint32_t sKh = st;
                const uint32_t sVh = st + AT_TILE_B;

                // ---- S = Q @ K^T (2-term) ----
                float sacc[8][4];
#pragma unroll
                for (int i = 0; i < 8; i++)
#pragma unroll
                    for (int c = 0; c < 4; c++) sacc[i][c] = 0.f;

#pragma unroll
                for (int kc = 0; kc < 4; kc++) {
#pragma unroll
                    for (int np = 0; np < 4; np++) {
                        const int krow = np * 16 + b_row;
                        const uint32_t addr = aswz(krow, kc * 2 + b_coff);
                        uint32_t bh4[4];
                        ldsm_x4(bh4, sKh + addr);
#pragma unroll
                        for (int j = 0; j < 2; j++) {
                            float* d = sacc[2 * np + j];
                            mma16816(d, qfh[kc], &bh4[2 * j]);
                            mma16816(d, qfl[kc], &bh4[2 * j]);
                        }
                    }
                }

                // ---- causal mask (global indices) ----
                if (need_mask) {
#pragma unroll
                    for (int nt = 0; nt < 8; nt++) {
                        const int colg = tile_k0 + nt * 8 + kq;
                        if (colg > grow)         sacc[nt][0] = -INFINITY;
                        if (colg + 1 > grow)     sacc[nt][1] = -INFINITY;
                        if (colg > grow + 8)     sacc[nt][2] = -INFINITY;
                        if (colg + 1 > grow + 8) sacc[nt][3] = -INFINITY;
                    }
                }

                // ---- online softmax ----
                float rm0 = -INFINITY, rm1 = -INFINITY;
#pragma unroll
                for (int nt = 0; nt < 8; nt++) {
                    rm0 = fmaxf(rm0, fmaxf(sacc[nt][0], sacc[nt][1]));
                    rm1 = fmaxf(rm1, fmaxf(sacc[nt][2], sacc[nt][3]));
                }
                rm0 = fmaxf(rm0, __shfl_xor_sync(0xffffffffu, rm0, 1));
                rm0 = fmaxf(rm0, __shfl_xor_sync(0xffffffffu, rm0, 2));
                rm1 = fmaxf(rm1, __shfl_xor_sync(0xffffffffu, rm1, 1));
                rm1 = fmaxf(rm1, __shfl_xor_sync(0xffffffffu, rm1, 2));

                float mn0 = fmaxf(m0, rm0), mn1 = fmaxf(m1, rm1);
                float c0 = __expf(m0 - mn0), c1 = __expf(m1 - mn1);
                m0 = mn0; m1 = mn1;
                l0 *= c0; l1 *= c1;
#pragma unroll
                for (int nt = 0; nt < 8; nt++) {
                    oa[nt][0] *= c0; oa[nt][1] *= c0;
                    oa[nt][2] *= c1; oa[nt][3] *= c1;
                }

                // ---- P = exp(S - m) per 16-key group; O += P @ V (2-term) ----
                float ps0 = 0.f, ps1 = 0.f;
#pragma unroll
                for (int kc2 = 0; kc2 < 4; kc2++) {
                    uint32_t pfh[4], pfl[4];
#pragma unroll
                    for (int j = 0; j < 2; j++) {
                        const int t = 2 * kc2 + j;
                        float p0 = __expf(sacc[t][0] - m0);
                        float p1 = __expf(sacc[t][1] - m0);
                        float p2 = __expf(sacc[t][2] - m1);
                        float p3 = __expf(sacc[t][3] - m1);
                        ps0 += p0 + p1; ps1 += p2 + p3;
                        __half h0, e0, h1, e1, h2, e2, h3, e3;
                        split2(p0, h0, e0); split2(p1, h1, e1);
                        split2(p2, h2, e2); split2(p3, h3, e3);
                        pfh[2 * j]     = pack_h2(h0, h1);
                        pfh[2 * j + 1] = pack_h2(h2, h3);
                        pfl[2 * j]     = pack_h2(e0, e1);
                        pfl[2 * j + 1] = pack_h2(e2, e3);
                    }
#pragma unroll
                    for (int dp = 0; dp < 4; dp++) {
                        const int vrow = kc2 * 16 + (lane & 7) + ((vg & 1) << 3);
                        const uint32_t addr = aswz(vrow, dp * 2 + (vg >> 1));
                        uint32_t bvh[4];
                        ldsm_x4_t(bvh, sVh + addr);
#pragma unroll
                        for (int j = 0; j < 2; j++) {
                            float* d = oa[2 * dp + j];
                            mma16816(d, pfh, &bvh[2 * j]);
                            mma16816(d, pfl, &bvh[2 * j]);
                        }
                    }
                }
                ps0 += __shfl_xor_sync(0xffffffffu, ps0, 1);
                ps0 += __shfl_xor_sync(0xffffffffu, ps0, 2);
                ps1 += __shfl_xor_sync(0xffffffffu, ps1, 1);
                ps1 += __shfl_xor_sync(0xffffffffu, ps1, 2);
                l0 += ps0; l1 += ps1;
            }
        }

        // ---- epilogue: normalize, split, write [B*S, H*hd] fp16 hi/lo ----
        const float il0 = 1.0f / l0, il1 = 1.0f / l1;
        const int b = bh >> 4, h = bh & 15;
        const int s0 = qt * 128 + wid * 16 + (lane >> 2);
        const size_t mrow0 = (size_t)(b * SEQ + s0) * DMODEL + h * HD;
        const size_t mrow1 = mrow0 + 8 * DMODEL;
#pragma unroll
        for (int nt = 0; nt < 8; nt++) {
            const int d = nt * 8 + kq;
            __half h0, e0, h1, e1;
            split2(oa[nt][0] * il0, h0, e0);
            split2(oa[nt][1] * il0, h1, e1);
            *(uint32_t*)(outh + mrow0 + d) = pack_h2(h0, h1);
            *(uint32_t*)(outl + mrow0 + d) = pack_h2(e0, e1);
            split2(oa[nt][2] * il1, h0, e0);
            split2(oa[nt][3] * il1, h1, e1);
            *(uint32_t*)(outh + mrow1 + d) = pack_h2(h0, h1);
            *(uint32_t*)(outl + mrow1 + d) = pack_h2(e0, e1);
        }
    }
}

// ---------------------------------------------------------------------------
extern "C" void kernel_launch(void* const* d_in, const int* in_sizes, int n_in,
                              void* d_out, int out_size)
{
    const float* x     = (const float*)d_in[0];
    const float* w_qkv = (const float*)d_in[1];
    const float* w_out = (const float*)d_in[2];
    float* out = (float*)d_out;

    __half *xh, *xl, *wqh, *woh, *ah, *al, *qh, *ql, *kh, *vh;
    float2* rope_tab;
    cudaGetSymbolAddress((void**)&xh,  g_xh);
    cudaGetSymbolAddress((void**)&xl,  g_xl);
    cudaGetSymbolAddress((void**)&wqh, g_wqh);
    cudaGetSymbolAddress((void**)&woh, g_woh);
    cudaGetSymbolAddress((void**)&ah,  g_ah);
    cudaGetSymbolAddress((void**)&al,  g_al);
    cudaGetSymbolAddress((void**)&qh,  g_qh);
    cudaGetSymbolAddress((void**)&ql,  g_ql);
    cudaGetSymbolAddress((void**)&kh,  g_kh);
    cudaGetSymbolAddress((void**)&vh,  g_vh);
    cudaGetSymbolAddress((void**)&rope_tab, g_rope_tab);

    cudaFuncSetAttribute(gemm_fp16x2_kernel,
                         cudaFuncAttributeMaxDynamicSharedMemorySize, G_SMEM_BYTES);
    cudaFuncSetAttribute(attn_tc_kernel,
                         cudaFuncAttributeMaxDynamicSharedMemorySize, AT_SMEM_B);

    // 1) rope table + convert input + both weight transposes
    rope_table_kernel<<<(SEQ * 32) / 256, 256>>>(rope_tab);
    {
        int n4 = M_ROWS * DMODEL / 4;
        convert_split4_kernel<<<(n4 + 255) / 256, 256>>>(
            (const float4*)x, (uint2*)xh, (uint2*)xl, n4);
    }
    transpose_both_kernel<<<dim3((QKV_N + DMODEL) / 32, DMODEL / 32), dim3(32, 32)>>>(
        w_qkv, w_out, wqh, woh);

    // 2) QKV projection + fused RoPE/split epilogue (tensor cores)
    gemm_fp16x2_kernel<<<dim3(QKV_N / 128, M_ROWS / 128), 256, G_SMEM_BYTES>>>(
        xh, xl, wqh, nullptr, qh, ql, kh, vh, M_ROWS, QKV_N, DMODEL, 1);

    // 3) Causal flash attention, paired q-tiles (writes out-proj A directly)
    attn_tc_kernel<<<dim3(SEQ / 256, BATCH * NH), 256, AT_SMEM_B>>>(
        qh, ql, kh, vh, ah, al);

    // 4) Output projection (tensor cores)
    gemm_fp16x2_kernel<<<dim3(DMODEL / 128, M_ROWS / 128), 256, G_SMEM_BYTES>>>(
        ah, al, woh, out, nullptr, nullptr, nullptr, nullptr,
        M_ROWS, DMODEL, DMODEL, 0);
}

// round 13
// speedup vs baseline: 5.9721x; 1.0178x over previous
#include <cuda_runtime.h>
#include <cuda_fp16.h>
#include <math.h>
#include <stdint.h>

#define BATCH  2
#define SEQ    2048
#define DMODEL 1024
#define NH     16
#define HD     64
#define M_ROWS (BATCH * SEQ)    // 4096
#define QKV_N  (3 * DMODEL)     // 3072

// ---------------------------------------------------------------------------
// Device scratch (fp16 emulation: A-side split hi/lo, B-side hi only)
// ---------------------------------------------------------------------------
__device__ __half g_xh[M_ROWS * DMODEL];
__device__ __half g_xl[M_ROWS * DMODEL];
__device__ __half g_wqh[QKV_N * DMODEL];   // [N,K] transposed, hi only
__device__ __half g_woh[DMODEL * DMODEL];  // [N,K] transposed, hi only
__device__ __half g_ah[M_ROWS * DMODEL];   // attention out hi (A of out-proj)
__device__ __half g_al[M_ROWS * DMODEL];

#define QKV_ELEMS (BATCH * NH * SEQ * HD)
__device__ __half g_qh[QKV_ELEMS];  // [B,H,S,hd], pre-scaled by 1/8
__device__ __half g_ql[QKV_ELEMS];
__device__ __half g_kh[QKV_ELEMS];  // hi only (B operand of QK^T)
__device__ __half g_vh[QKV_ELEMS];  // hi only (B operand of PV)

__device__ float2 g_rope_tab[SEQ * 32];    // (cos, sin) per (s, j)

// ---------------------------------------------------------------------------
// Baseline-PTX helpers
// ---------------------------------------------------------------------------
__device__ __forceinline__ uint32_t smem_u32(const void* p) {
    uint32_t a;
    asm("{ .reg .u64 t; cvta.to.shared.u64 t, %1; cvt.u32.u64 %0, t; }"
        : "=r"(a) : "l"(p));
    return a;
}

#define CP_ASYNC_16(smem, gptr) \
    asm volatile("cp.async.cg.shared.global [%0], [%1], 16;\n" \
        :: "r"(smem), "l"(gptr))
#define CP_ASYNC_COMMIT() asm volatile("cp.async.commit_group;\n")
#define CP_ASYNC_WAIT(n)  asm volatile("cp.async.wait_group %0;\n" :: "n"(n))

__device__ __forceinline__ void ldsm_x4(uint32_t* r, uint32_t addr) {
    asm volatile("ldmatrix.sync.aligned.m8n8.x4.shared.b16 {%0,%1,%2,%3}, [%4];\n"
        : "=r"(r[0]), "=r"(r[1]), "=r"(r[2]), "=r"(r[3]) : "r"(addr));
}
__device__ __forceinline__ void ldsm_x4_t(uint32_t* r, uint32_t addr) {
    asm volatile("ldmatrix.sync.aligned.m8n8.x4.trans.shared.b16 {%0,%1,%2,%3}, [%4];\n"
        : "=r"(r[0]), "=r"(r[1]), "=r"(r[2]), "=r"(r[3]) : "r"(addr));
}

// D(f32) += A(f16) * B(f16): m16n8k16
__device__ __forceinline__ void mma16816(float* d, const uint32_t* a, const uint32_t* b) {
    asm volatile(
        "mma.sync.aligned.m16n8k16.row.col.f32.f16.f16.f32 "
        "{%0,%1,%2,%3}, {%4,%5,%6,%7}, {%8,%9}, {%0,%1,%2,%3};\n"
        : "+f"(d[0]), "+f"(d[1]), "+f"(d[2]), "+f"(d[3])
        : "r"(a[0]), "r"(a[1]), "r"(a[2]), "r"(a[3]), "r"(b[0]), "r"(b[1]));
}

// ---------------------------------------------------------------------------
// fp32 -> (hi, lo) fp16 split helpers
// ---------------------------------------------------------------------------
__device__ __forceinline__ void split2(float x, __half& h, __half& l) {
    h = __float2half(x);
    l = __float2half(x - __half2float(h));
}
__device__ __forceinline__ uint32_t pack_h2(__half a, __half b) {
    __half2 t; t.x = a; t.y = b;
    return *(uint32_t*)&t;
}

// ---------------------------------------------------------------------------
// Fused prep: convert x (blocks 0..4095), transpose both weights
// (blocks 4096..8191), rope table (blocks 8192..8447). 256 threads.
// ---------------------------------------------------------------------------
#define PREP_CONV_BLOCKS  4096     // n4 = 4096*256 elements of float4
#define PREP_TRANS_BLOCKS 4096     // 128 n-tiles x 32 k-tiles of 32x32
#define PREP_ROPE_BLOCKS  256      // SEQ*32 / 256
#define PREP_BLOCKS (PREP_CONV_BLOCKS + PREP_TRANS_BLOCKS + PREP_ROPE_BLOCKS)

__global__ void __launch_bounds__(256)
prep_kernel(const float4* __restrict__ x4,
            const float* __restrict__ Wq, const float* __restrict__ Wo,
            uint2* __restrict__ xh, uint2* __restrict__ xl,
            __half* __restrict__ Tq, __half* __restrict__ To,
            float2* __restrict__ tab)
{
    const int blk = blockIdx.x;
    const int tid = threadIdx.x;

    if (blk < PREP_CONV_BLOCKS) {
        int i = blk * 256 + tid;                 // < M_ROWS*DMODEL/4
        float4 v = x4[i];
        __half h0, l0, h1, l1, h2, l2, h3, l3;
        split2(v.x, h0, l0); split2(v.y, h1, l1);
        split2(v.z, h2, l2); split2(v.w, h3, l3);
        xh[i] = make_uint2(pack_h2(h0, h1), pack_h2(h2, h3));
        xl[i] = make_uint2(pack_h2(l0, l1), pack_h2(l2, l3));
    } else if (blk < PREP_CONV_BLOCKS + PREP_TRANS_BLOCKS) {
        __shared__ float tile[32][33];
        const int t = blk - PREP_CONV_BLOCKS;
        const int tile_n = t & 127;              // 0..127 (4096 n-cols / 32)
        const int tile_k = t >> 7;               // 0..31
        const int tx = tid & 31;
        const int ty0 = tid >> 5;                // 0..7
        const int n = tile_n * 32 + tx;
#pragma unroll
        for (int r = 0; r < 4; r++) {
            const int ty = ty0 + r * 8;
            const int k = tile_k * 32 + ty;
            float v = (n < QKV_N) ? Wq[(size_t)k * QKV_N + n]
                                  : Wo[(size_t)k * DMODEL + (n - QKV_N)];
            tile[ty][tx] = v;
        }
        __syncthreads();
#pragma unroll
        for (int r = 0; r < 4; r++) {
            const int ty = ty0 + r * 8;
            const int nt = tile_n * 32 + ty;
            const int kt = tile_k * 32 + tx;
            __half hv = __float2half(tile[tx][ty]);
            if (nt < QKV_N) Tq[(size_t)nt * DMODEL + kt] = hv;
            else            To[(size_t)(nt - QKV_N) * DMODEL + kt] = hv;
        }
    } else {
        int i = (blk - PREP_CONV_BLOCKS - PREP_TRANS_BLOCKS) * 256 + tid;  // < SEQ*32
        int j = i & 31, s = i >> 5;
        float inv_freq = powf(10000.0f, -(float)j * (1.0f / 32.0f));
        float sn, cs;
        sincosf((float)s * inv_freq, &sn, &cs);
        tab[i] = make_float2(cs, sn);
    }
}

// ---------------------------------------------------------------------------
// Tensor-core GEMM: C = A@B, fp16 x 2-term fp32 emulation (A split, B hi).
// 128 threads = 4 warps (2m x 2n), warp tile 64x64 -> 5.3 MMA/ldsm
// (smem-traffic bound relief vs 8-warp 32x64 layout).
// mode 0: store fp32 C.  mode 1: fused RoPE/split epilogue for QKV.
// ---------------------------------------------------------------------------
#define G_BK 32
#define G_TILE_B  (128 * 64)            // 8192
#define G_STAGE_B (3 * G_TILE_B)        // 24576: Ahi, Alo, Bh
#define G_STAGES  3
#define G_SMEM_BYTES (G_STAGES * G_STAGE_B)  // 73728

__device__ __forceinline__ uint32_t gswz(int row, int chunk) {
    return (uint32_t)(row * 64 + ((chunk ^ ((row >> 1) & 3)) << 4));
}

__global__ void __launch_bounds__(128)
gemm_fp16x2_kernel(const __half* __restrict__ Ahi,
                   const __half* __restrict__ Alo,
                   const __half* __restrict__ Bh,
                   float* __restrict__ C,
                   __half* __restrict__ qh, __half* __restrict__ ql,
                   __half* __restrict__ kh, __half* __restrict__ vh,
                   int M, int N, int K, int mode)
{
    extern __shared__ __align__(128) char dsm[];
    const uint32_t smem_base = smem_u32(dsm);

    const int tid = threadIdx.x;
    const int wid = tid >> 5;          // 0..3
    const int lane = tid & 31;
    const int warp_m = wid >> 1;       // 0..1 -> 64-row slice
    const int warp_n = wid & 1;        // 0..1 -> 64-col slice
    const int m0 = blockIdx.y * 128;
    const int n0 = blockIdx.x * 128;

    const __half* gsrc[3] = {Ahi, Alo, Bh};

    float acc[4][8][4];
#pragma unroll
    for (int i = 0; i < 4; i++)
#pragma unroll
        for (int j = 0; j < 8; j++)
#pragma unroll
            for (int c = 0; c < 4; c++) acc[i][j][c] = 0.f;

    const int nchunk = K / G_BK;

    auto issue = [&](int ci) {
        const int k0 = ci * G_BK;
        const uint32_t st = smem_base + (ci % G_STAGES) * G_STAGE_B;
#pragma unroll
        for (int i = 0; i < 12; i++) {
            const int tile = i >> 2;                       // 0..2
            const int idx = ((i & 3) << 7) | tid;          // 0..511
            const int r = idx >> 2;                        // 0..127
            const int c = idx & 3;                         // 16B chunk
            const int grow = (tile < 2 ? m0 : n0) + r;
            const __half* gp = gsrc[tile] + (size_t)grow * K + k0 + c * 8;
            CP_ASYNC_16(st + tile * G_TILE_B + gswz(r, c), gp);
        }
        CP_ASYNC_COMMIT();
    };

    issue(0);
    issue(1);

    const int a_row_off = (lane & 15);
    const int a_coff    = (lane >> 4) & 1;
    const int b_row_off = ((lane & 16) >> 1) + (lane & 7);
    const int b_coff    = (lane & 8) >> 3;

#pragma unroll 1
    for (int ci = 0; ci < nchunk; ci++) {
        CP_ASYNC_WAIT(1);
        __syncthreads();
        if (ci + 2 < nchunk) issue(ci + 2);

        const uint32_t st = smem_base + (ci % G_STAGES) * G_STAGE_B;
        const uint32_t sAhi = st;
        const uint32_t sAlo = st + G_TILE_B;
        const uint32_t sBh  = st + 2 * G_TILE_B;

#pragma unroll
        for (int ks = 0; ks < 2; ks++) {
            uint32_t ahi[4][4], alo[4][4];
#pragma unroll
            for (int mt = 0; mt < 4; mt++) {
                const int ar = warp_m * 64 + mt * 16 + a_row_off;
                const uint32_t aoff = gswz(ar, ks * 2 + a_coff);
                ldsm_x4(ahi[mt], sAhi + aoff);
                ldsm_x4(alo[mt], sAlo + aoff);
            }
#pragma unroll
            for (int ntp = 0; ntp < 4; ntp++) {
                const int br = warp_n * 64 + ntp * 16 + b_row_off;
                const uint32_t boff = gswz(br, ks * 2 + b_coff);
                uint32_t bh4[4];
                ldsm_x4(bh4, sBh + boff);
#pragma unroll
                for (int mt = 0; mt < 4; mt++)
#pragma unroll
                    for (int j = 0; j < 2; j++) {
                        float* d = acc[mt][2 * ntp + j];
                        mma16816(d, ahi[mt], &bh4[2 * j]);
                        mma16816(d, alo[mt], &bh4[2 * j]);
                    }
            }
        }
    }

    const int quad = lane >> 2;
    const int tq = lane & 3;

    if (mode == 0) {
        float* Cw = C + (size_t)(m0 + warp_m * 64) * N + n0 + warp_n * 64;
#pragma unroll
        for (int mt = 0; mt < 4; mt++)
#pragma unroll
            for (int nt = 0; nt < 8; nt++) {
                const int r = mt * 16 + quad;
                const int c = nt * 8 + tq * 2;
                *(float2*)(Cw + (size_t)r * N + c) =
                    make_float2(acc[mt][nt][0], acc[mt][nt][1]);
                *(float2*)(Cw + (size_t)(r + 8) * N + c) =
                    make_float2(acc[mt][nt][2], acc[mt][nt][3]);
            }
        return;
    }

    // ---- mode 1: fused RoPE + split epilogue for QKV ----
    const int ng0 = n0 + warp_n * 64;          // 64-aligned -> single head
    const int sec = ng0 >> 10;                 // 0=q, 1=k, 2=v
    const int hh  = (ng0 & 1023) >> 6;
    __half* ph = (sec == 0) ? qh : (sec == 1) ? kh : vh;

#pragma unroll
    for (int mt = 0; mt < 4; mt++) {
#pragma unroll
        for (int half = 0; half < 2; half++) {
            const int r_g = m0 + warp_m * 64 + mt * 16 + quad + half * 8;
            const int b = r_g >> 11, s = r_g & 2047;
            const size_t dst = ((size_t)((b * NH + hh) * SEQ) + s) * HD;
            const float2* trow = g_rope_tab + s * 32;
#pragma unroll
            for (int nt = 0; nt < 8; nt++) {
                const int d0 = nt * 8 + tq * 2;
                float v0 = acc[mt][nt][half * 2 + 0];
                float v1 = acc[mt][nt][half * 2 + 1];
                float r0, r1;
                if (sec < 2) {
                    const float p0 = acc[mt][nt ^ 4][half * 2 + 0];
                    const float p1 = acc[mt][nt ^ 4][half * 2 + 1];
                    const int j0 = d0 & 31;
                    const float2 t0 = trow[j0];
                    const float2 t1 = trow[j0 + 1];
                    if (nt < 4) { r0 = v0 * t0.x - p0 * t0.y; r1 = v1 * t1.x - p1 * t1.y; }
                    else        { r0 = v0 * t0.x + p0 * t0.y; r1 = v1 * t1.x + p1 * t1.y; }
                    if (sec == 0) { r0 *= 0.125f; r1 *= 0.125f; }
                } else { r0 = v0; r1 = v1; }
                if (sec == 0) {
                    __half h0, e0, h1, e1;
                    split2(r0, h0, e0);
                    split2(r1, h1, e1);
                    *(uint32_t*)(qh + dst + d0) = pack_h2(h0, h1);
                    *(uint32_t*)(ql + dst + d0) = pack_h2(e0, e1);
                } else {
                    *(uint32_t*)(ph + dst + d0) =
                        pack_h2(__float2half(r0), __float2half(r1));
                }
            }
        }
    }
}

// ---------------------------------------------------------------------------
// Tensor-core causal flash attention (fp16 x 2-term emulation).
// 256 threads = 8 warps, q-tile 128 (16 rows/warp). Key tiles of 64.
// Q-tile pairing: block bx processes q-tiles {15-bx, bx} -> uniform 34
// key-tile units per block. 3-stage cp.async pipeline.
// ---------------------------------------------------------------------------
#define AT_TILE_B  (64 * 128)             // 8192
#define AT_STAGE_B (2 * AT_TILE_B)        // 16384: Kh, Vh
#define AT_STAGES  3
#define AT_SMEM_B  (AT_STAGES * AT_STAGE_B)  // 49152

__device__ __forceinline__ uint32_t aswz(int row, int chunk) {
    return (uint32_t)(row * 128 + ((chunk ^ (row & 7)) << 4));
}

__global__ void __launch_bounds__(256)
attn_tc_kernel(const __half* __restrict__ qh, const __half* __restrict__ ql,
               const __half* __restrict__ kh, const __half* __restrict__ vh,
               __half* __restrict__ outh, __half* __restrict__ outl)
{
    extern __shared__ __align__(128) char dsm[];
    const uint32_t sb = smem_u32(dsm);

    const int bh = blockIdx.y;
    const int tid = threadIdx.x;
    const int wid = tid >> 5;
    const int lane = tid & 31;
    const int kq = (lane & 3) * 2;               // fragment col offset
    const size_t base = (size_t)bh * SEQ * HD;

    const __half* khp = kh + base;
    const __half* vhp = vh + base;

    auto issue = [&](int kt) {
        const uint32_t st = sb + (kt % AT_STAGES) * AT_STAGE_B;
        const __half* srcs[2] = {khp, vhp};
        const int kr0 = kt * 64;
#pragma unroll
        for (int t = 0; t < 2; t++) {
#pragma unroll
            for (int i = 0; i < 2; i++) {
                int c = i * 256 + tid;           // 0..511
                int row = c >> 3, col = c & 7;
                CP_ASYNC_16(st + t * AT_TILE_B + aswz(row, col),
                            srcs[t] + (size_t)(kr0 + row) * HD + col * 8);
            }
        }
        CP_ASYNC_COMMIT();
    };

    const int b_row = ((lane & 16) >> 1) + (lane & 7);
    const int b_coff = (lane & 8) >> 3;
    const int vg    = lane >> 3;
    const int rloc = wid * 16 + (lane >> 2);     // local q row, +8 pair

#pragma unroll 1
    for (int ps = 0; ps < 2; ps++) {
        const int qt = ps ? (int)blockIdx.x : (SEQ / 128 - 1 - (int)blockIdx.x);
        const int grow = qt * 128 + rloc;        // global q row

        // ---- Q fragments (register resident) ----
        uint32_t qfh[4][4], qfl[4][4];
#pragma unroll
        for (int kc = 0; kc < 4; kc++) {
            size_t o = base + (size_t)grow * HD + kc * 16 + kq;
            qfh[kc][0] = *(const uint32_t*)(qh + o);
            qfh[kc][1] = *(const uint32_t*)(qh + o + 8 * HD);
            qfh[kc][2] = *(const uint32_t*)(qh + o + 8);
            qfh[kc][3] = *(const uint32_t*)(qh + o + 8 * HD + 8);
            qfl[kc][0] = *(const uint32_t*)(ql + o);
            qfl[kc][1] = *(const uint32_t*)(ql + o + 8 * HD);
            qfl[kc][2] = *(const uint32_t*)(ql + o + 8);
            qfl[kc][3] = *(const uint32_t*)(ql + o + 8 * HD + 8);
        }

        float oa[8][4];
#pragma unroll
        for (int i = 0; i < 8; i++)
#pragma unroll
            for (int c = 0; c < 4; c++) oa[i][c] = 0.f;
        float m0 = -INFINITY, m1 = -INFINITY, l0 = 0.f, l1 = 0.f;

        const int nkt = 2 * qt + 2;              // key tiles: 0 .. 2qt+1

        __syncthreads();                         // smem safe for reuse
        issue(0);
        if (nkt > 1) issue(1);

#pragma unroll 1
        for (int kt = 0; kt < nkt; kt++) {
            if (kt + 1 < nkt) { CP_ASYNC_WAIT(1); } else { CP_ASYNC_WAIT(0); }
            __syncthreads();
            if (kt + 2 < nkt) issue(kt + 2);

            const int tile_k0 = kt * 64;
            const int wrow_min = qt * 128 + wid * 16;
            const bool full_skip = tile_k0 > wrow_min + 15;
            const bool need_mask = !full_skip && (tile_k0 + 63 > wrow_min);

            if (!full_skip) {
                const uint32_t st  = sb + (kt % AT_STAGES) * AT_STAGE_B;
                const uint32_t sKh = st;
                const uint32_t sVh = st + AT_TILE_B;

                // ---- S = Q @ K^T (2-term) ----
                float sacc[8][4];
#pragma unroll
                for (int i = 0; i < 8; i++)
#pragma unroll
                    for (int c = 0; c < 4; c++) sacc[i][c] = 0.f;

#pragma unroll
                for (int kc = 0; kc < 4; kc++) {
#pragma unroll
                    for (int np = 0; np < 4; np++) {
                        const int krow = np * 16 + b_row;
                        const uint32_t addr = aswz(krow, kc * 2 + b_coff);
                        uint32_t bh4[4];
                        ldsm_x4(bh4, sKh + addr);
#pragma unroll
                        for (int j = 0; j < 2; j++) {
                            float* d = sacc[2 * np + j];
                            mma16816(d, qfh[kc], &bh4[2 * j]);
                            mma16816(d, qfl[kc], &bh4[2 * j]);
                        }
                    }
                }

                // ---- causal mask (global indices) ----
                if (need_mask) {
#pragma unroll
                    for (int nt = 0; nt < 8; nt++) {
                        const int colg = tile_k0 + nt * 8 + kq;
                        if (colg > grow)         sacc[nt][0] = -INFINITY;
                        if (colg + 1 > grow)     sacc[nt][1] = -INFINITY;
                        if (colg > grow + 8)     sacc[nt][2] = -INFINITY;
                        if (colg + 1 > grow + 8) sacc[nt][3] = -INFINITY;
                    }
                }

                // ---- online softmax ----
                float rm0 = -INFINITY, rm1 = -INFINITY;
#pragma unroll
                for (int nt = 0; nt < 8; nt++) {
                    rm0 = fmaxf(rm0, fmaxf(sacc[nt][0], sacc[nt][1]));
                    rm1 = fmaxf(rm1, fmaxf(sacc[nt][2], sacc[nt][3]));
                }
                rm0 = fmaxf(rm0, __shfl_xor_sync(0xffffffffu, rm0, 1));
                rm0 = fmaxf(rm0, __shfl_xor_sync(0xffffffffu, rm0, 2));
                rm1 = fmaxf(rm1, __shfl_xor_sync(0xffffffffu, rm1, 1));
                rm1 = fmaxf(rm1, __shfl_xor_sync(0xffffffffu, rm1, 2));

                float mn0 = fmaxf(m0, rm0), mn1 = fmaxf(m1, rm1);
                float c0 = __expf(m0 - mn0), c1 = __expf(m1 - mn1);
                m0 = mn0; m1 = mn1;
                l0 *= c0; l1 *= c1;
#pragma unroll
                for (int nt = 0; nt < 8; nt++) {
                    oa[nt][0] *= c0; oa[nt][1] *= c0;
                    oa[nt][2] *= c1; oa[nt][3] *= c1;
                }

                // ---- P = exp(S - m) per 16-key group; O += P @ V (2-term) ----
                float ps0 = 0.f, ps1 = 0.f;
#pragma unroll
                for (int kc2 = 0; kc2 < 4; kc2++) {
                    uint32_t pfh[4], pfl[4];
#pragma unroll
                    for (int j = 0; j < 2; j++) {
                        const int t = 2 * kc2 + j;
                        float p0 = __expf(sacc[t][0] - m0);
                        float p1 = __expf(sacc[t][1] - m0);
                        float p2 = __expf(sacc[t][2] - m1);
                        float p3 = __expf(sacc[t][3] - m1);
                        ps0 += p0 + p1; ps1 += p2 + p3;
                        __half h0, e0, h1, e1, h2, e2, h3, e3;
                        split2(p0, h0, e0); split2(p1, h1, e1);
                        split2(p2, h2, e2); split2(p3, h3, e3);
                        pfh[2 * j]     = pack_h2(h0, h1);
                        pfh[2 * j + 1] = pack_h2(h2, h3);
                        pfl[2 * j]     = pack_h2(e0, e1);
                        pfl[2 * j + 1] = pack_h2(e2, e3);
                    }
#pragma unroll
                    for (int dp = 0; dp < 4; dp++) {
                        const int vrow = kc2 * 16 + (lane & 7) + ((vg & 1) << 3);
                        const uint32_t addr = aswz(vrow, dp * 2 + (vg >> 1));
                        uint32_t bvh[4];
                        ldsm_x4_t(bvh, sVh + addr);
#pragma unroll
                        for (int j = 0; j < 2; j++) {
                            float* d = oa[2 * dp + j];
                            mma16816(d, pfh, &bvh[2 * j]);
                            mma16816(d, pfl, &bvh[2 * j]);
                        }
                    }
                }
                ps0 += __shfl_xor_sync(0xffffffffu, ps0, 1);
                ps0 += __shfl_xor_sync(0xffffffffu, ps0, 2);
                ps1 += __shfl_xor_sync(0xffffffffu, ps1, 1);
                ps1 += __shfl_xor_sync(0xffffffffu, ps1, 2);
                l0 += ps0; l1 += ps1;
            }
        }

        // ---- epilogue: normalize, split, write [B*S, H*hd] fp16 hi/lo ----
        const float il0 = 1.0f / l0, il1 = 1.0f / l1;
        const int b = bh >> 4, h = bh & 15;
        const int s0 = qt * 128 + wid * 16 + (lane >> 2);
        const size_t mrow0 = (size_t)(b * SEQ + s0) * DMODEL + h * HD;
        const size_t mrow1 = mrow0 + 8 * DMODEL;
#pragma unroll
        for (int nt = 0; nt < 8; nt++) {
            const int d = nt * 8 + kq;
            __half h0, e0, h1, e1;
            split2(oa[nt][0] * il0, h0, e0);
            split2(oa[nt][1] * il0, h1, e1);
            *(uint32_t*)(outh + mrow0 + d) = pack_h2(h0, h1);
            *(uint32_t*)(outl + mrow0 + d) = pack_h2(e0, e1);
            split2(oa[nt][2] * il1, h0, e0);
            split2(oa[nt][3] * il1, h1, e1);
            *(uint32_t*)(outh + mrow1 + d) = pack_h2(h0, h1);
            *(uint32_t*)(outl + mrow1 + d) = pack_h2(e0, e1);
        }
    }
}

// ---------------------------------------------------------------------------
extern "C" void kernel_launch(void* const* d_in, const int* in_sizes, int n_in,
                              void* d_out, int out_size)
{
    const float* x     = (const float*)d_in[0];
    const float* w_qkv = (const float*)d_in[1];
    const float* w_out = (const float*)d_in[2];
    float* out = (float*)d_out;

    __half *xh, *xl, *wqh, *woh, *ah, *al, *qh, *ql, *kh, *vh;
    float2* rope_tab;
    cudaGetSymbolAddress((void**)&xh,  g_xh);
    cudaGetSymbolAddress((void**)&xl,  g_xl);
    cudaGetSymbolAddress((void**)&wqh, g_wqh);
    cudaGetSymbolAddress((void**)&woh, g_woh);
    cudaGetSymbolAddress((void**)&ah,  g_ah);
    cudaGetSymbolAddress((void**)&al,  g_al);
    cudaGetSymbolAddress((void**)&qh,  g_qh);
    cudaGetSymbolAddress((void**)&ql,  g_ql);
    cudaGetSymbolAddress((void**)&kh,  g_kh);
    cudaGetSymbolAddress((void**)&vh,  g_vh);
    cudaGetSymbolAddress((void**)&rope_tab, g_rope_tab);

    cudaFuncSetAttribute(gemm_fp16x2_kernel,
                         cudaFuncAttributeMaxDynamicSharedMemorySize, G_SMEM_BYTES);
    cudaFuncSetAttribute(attn_tc_kernel,
                         cudaFuncAttributeMaxDynamicSharedMemorySize, AT_SMEM_B);

    // 1) fused prep: convert x + both weight transposes + rope table
    prep_kernel<<<PREP_BLOCKS, 256>>>(
        (const float4*)x, w_qkv, w_out,
        (uint2*)xh, (uint2*)xl, wqh, woh, rope_tab);

    // 2) QKV projection + fused RoPE/split epilogue (tensor cores)
    gemm_fp16x2_kernel<<<dim3(QKV_N / 128, M_ROWS / 128), 128, G_SMEM_BYTES>>>(
        xh, xl, wqh, nullptr, qh, ql, kh, vh, M_ROWS, QKV_N, DMODEL, 1);

    // 3) Causal flash attention, paired q-tiles (writes out-proj A directly)
    attn_tc_kernel<<<dim3(SEQ / 256, BATCH * NH), 256, AT_SMEM_B>>>(
        qh, ql, kh, vh, ah, al);

    // 4) Output projection (tensor cores)
    gemm_fp16x2_kernel<<<dim3(DMODEL / 128, M_ROWS / 128), 128, G_SMEM_BYTES>>>(
        ah, al, woh, out, nullptr, nullptr, nullptr, nullptr,
        M_ROWS, DMODEL, DMODEL, 0);
}